// round 1
// baseline (speedup 1.0000x reference)
#include <cuda_runtime.h>
#include <math.h>

#define MEMD 172
#define FEATD 172
#define TDD 100
#define KNB 10
#define DHD 86
#define MSGD 616          // 2*MEM + FEAT + TD
#define G3 516            // 3*MEM
#define NMAX 100000
#define RB 256            // reduction partial blocks

// ---------------- scratch (static device globals; no allocation) ----------------
__device__ int   g_lastpos[NMAX];
__device__ float g_M[NMAX * MSGD];        // selected messages   [N,616]
__device__ float g_GI[NMAX * G3];         // m @ WiT + bi        [N,516]
__device__ float g_GH[NMAX * G3];         // mem @ WhT + bh      [N,516]
__device__ float g_h[NMAX * MEMD];        // updated mem + feats [N,172]
__device__ float g_QKV[NMAX * G3];        // h @ [Wq1|Wk1|Wv1]   [N,516]
__device__ float g_agg[NMAX * MEMD];      // attention output    [N,172]
__device__ float g_T1[NMAX * MEMD];       // relu(cat@W1+b1)     [N,172]
__device__ float g_emb[NMAX * MEMD];      // embedding           [N,172]
__device__ float g_WiT[MSGD * G3];
__device__ float g_WhT[MEMD * G3];
__device__ float g_Bqkv[MEMD * G3];
__device__ float g_qconst[MEMD];
__device__ float g_partial[RB * MEMD];

// robust cos for large args (fast-math-safe): fp64 2*pi range reduction
__device__ __forceinline__ float cos_acc(float x) {
    double xd = (double)x;
    double q = rint(xd * 0.15915494309189535);      // x / (2*pi)
    float r = (float)(xd - q * 6.283185307179586);
    return cosf(r);
}

// ---------------- small prep kernels ----------------
__global__ void k_init(int N) {
    int i = blockIdx.x * blockDim.x + threadIdx.x;
    if (i < N) g_lastpos[i] = -1;
}

__global__ void k_scatter(const int* __restrict__ src, const int* __restrict__ dst, int E) {
    int e = blockIdx.x * blockDim.x + threadIdx.x;
    if (e < E) {
        atomicMax(&g_lastpos[src[e]], e);
        atomicMax(&g_lastpos[dst[e]], E + e);
    }
}

__global__ void k_prep_wit(const float* __restrict__ Wi) {   // WiT[k*516+j] = Wi[j*616+k]
    int idx = blockIdx.x * blockDim.x + threadIdx.x;
    if (idx < MSGD * G3) {
        int k = idx / G3, j = idx - k * G3;
        g_WiT[idx] = Wi[j * MSGD + k];
    }
}

__global__ void k_prep_wht(const float* __restrict__ Wh) {   // WhT[k*516+j] = Wh[j*172+k]
    int idx = blockIdx.x * blockDim.x + threadIdx.x;
    if (idx < MEMD * G3) {
        int k = idx / G3, j = idx - k * G3;
        g_WhT[idx] = Wh[j * MEMD + k];
    }
}

__global__ void k_prep_bqkv(const float* __restrict__ Wq, const float* __restrict__ Wk,
                            const float* __restrict__ Wv) {
    int idx = blockIdx.x * blockDim.x + threadIdx.x;
    if (idx < MEMD * G3) {
        int k = idx / G3, j = idx - k * G3;
        int sel = j / MEMD, jj = j - sel * MEMD;
        const float* W = (sel == 0) ? Wq : ((sel == 1) ? Wk : Wv);
        g_Bqkv[idx] = W[k * MEMD + jj];
    }
}

__global__ void k_prep_qconst(const float* __restrict__ Wq, const float* __restrict__ tb) {
    int j = threadIdx.x;
    if (j < MEMD) {
        float s = 0.f;
        for (int t = 0; t < TDD; t++)
            s += cos_acc(tb[t]) * Wq[(MEMD + t) * MEMD + j];
        g_qconst[j] = s;
    }
}

// ---------------- build selected message matrix [N,616] ----------------
__global__ void k_build_m(const float* __restrict__ mem, const float* __restrict__ lu,
                          const float* __restrict__ ts, const float* __restrict__ ef,
                          const float* __restrict__ tw, const float* __restrict__ tb,
                          const int* __restrict__ src, const int* __restrict__ dst,
                          int Nn, int E) {
    int n = blockIdx.x;
    if (n >= Nn) return;
    int tid = threadIdx.x;
    __shared__ int s_a, s_b, s_e, s_has;
    __shared__ float s_dt;
    if (tid == 0) {
        int p = g_lastpos[n];
        if (p < 0) {
            s_has = 0;
        } else {
            s_has = 1;
            int e, a, b;
            if (p < E) { e = p;     a = src[e]; b = dst[e]; }
            else       { e = p - E; a = dst[e]; b = src[e]; }
            s_e = e; s_a = a; s_b = b;
            s_dt = ts[e] - lu[a];
        }
    }
    __syncthreads();
    float* row = g_M + (size_t)n * MSGD;
    if (!s_has) {
        for (int i = tid; i < MSGD; i += blockDim.x) row[i] = 0.f;
        return;
    }
    int a = s_a, b = s_b, e = s_e;
    float dt = s_dt;
    for (int i = tid; i < MSGD; i += blockDim.x) {
        float v;
        if (i < MEMD)            v = mem[(size_t)a * MEMD + i];
        else if (i < 2 * MEMD)   v = mem[(size_t)b * MEMD + (i - MEMD)];
        else if (i < 2 * MEMD + FEATD) v = ef[(size_t)e * FEATD + (i - 2 * MEMD)];
        else { int t = i - (2 * MEMD + FEATD); v = cos_acc(dt * tw[t] + tb[t]); }
        row[i] = v;
    }
}

// ---------------- generic tiled fp32 GEMM: C = A[M,K] @ B[K,N] (+bias,+accum,+relu) ----------------
#define BM 64
#define BN 64
#define BK 16
__global__ void k_gemm(const float* __restrict__ A, const float* __restrict__ B,
                       const float* __restrict__ bias, float* __restrict__ C,
                       int M, int N, int K, int accum, int relu) {
    __shared__ float As[BK][BM + 4];
    __shared__ float Bs[BK][BN + 4];
    int tid = threadIdx.x;
    int row0 = blockIdx.y * BM, col0 = blockIdx.x * BN;
    int tx = tid & 15, ty = tid >> 4;
    int lka = tid & 15, lra = tid >> 4;     // A loads: 16 k-cols x 16 rows x4
    int lcb = tid & 63, lkb = tid >> 6;     // B loads: 64 cols x 4 k-rows x4
    float acc[4][4];
#pragma unroll
    for (int i = 0; i < 4; i++)
#pragma unroll
        for (int j = 0; j < 4; j++) acc[i][j] = 0.f;

    for (int k0 = 0; k0 < K; k0 += BK) {
#pragma unroll
        for (int i = 0; i < 4; i++) {
            int r = lra + i * 16;
            int gr = row0 + r, gk = k0 + lka;
            As[lka][r] = (gr < M && gk < K) ? A[(size_t)gr * K + gk] : 0.f;
        }
#pragma unroll
        for (int i = 0; i < 4; i++) {
            int kk = lkb + i * 4;
            int gk = k0 + kk, gc = col0 + lcb;
            Bs[kk][lcb] = (gk < K && gc < N) ? B[(size_t)gk * N + gc] : 0.f;
        }
        __syncthreads();
#pragma unroll
        for (int kk = 0; kk < BK; kk++) {
            float a[4], b[4];
#pragma unroll
            for (int i = 0; i < 4; i++) a[i] = As[kk][ty * 4 + i];
#pragma unroll
            for (int j = 0; j < 4; j++) b[j] = Bs[kk][tx * 4 + j];
#pragma unroll
            for (int i = 0; i < 4; i++)
#pragma unroll
                for (int j = 0; j < 4; j++) acc[i][j] += a[i] * b[j];
        }
        __syncthreads();
    }
#pragma unroll
    for (int i = 0; i < 4; i++) {
        int gr = row0 + ty * 4 + i;
        if (gr >= M) continue;
#pragma unroll
        for (int j = 0; j < 4; j++) {
            int gc = col0 + tx * 4 + j;
            if (gc >= N) continue;
            float v = acc[i][j];
            if (bias) v += bias[gc];
            size_t idx = (size_t)gr * N + gc;
            if (accum) v += C[idx];
            if (relu) v = fmaxf(v, 0.f);
            C[idx] = v;
        }
    }
}

// ---------------- GRU gating + h = mem_upd + node_features ----------------
__global__ void k_gate(const float* __restrict__ mem, const float* __restrict__ nf, int Nn) {
    int idx = blockIdx.x * blockDim.x + threadIdx.x;
    if (idx >= Nn * MEMD) return;
    int n = idx / MEMD, d = idx - n * MEMD;
    float mv = mem[idx];
    float hv;
    if (g_lastpos[n] >= 0) {
        const float* gi = g_GI + (size_t)n * G3;
        const float* gh = g_GH + (size_t)n * G3;
        float r = 1.f / (1.f + expf(-(gi[d] + gh[d])));
        float z = 1.f / (1.f + expf(-(gi[MEMD + d] + gh[MEMD + d])));
        float g = tanhf(gi[2 * MEMD + d] + r * gh[2 * MEMD + d]);
        hv = (1.f - z) * g + z * mv;
    } else {
        hv = mv;
    }
    g_h[idx] = hv + nf[idx];
}

// ---------------- temporal attention (1 block = 1 node, 128 threads) ----------------
__global__ void k_attn(const float* __restrict__ Wk_full, const float* __restrict__ Wv_full,
                       const int* __restrict__ nbi, const float* __restrict__ nts,
                       const float* __restrict__ tw, const float* __restrict__ tb,
                       const float* __restrict__ ts, int Nn, int E) {
    int n = blockIdx.x;
    if (n >= Nn) return;
    int tid = threadIdx.x;
    __shared__ float s_q[MEMD];
    __shared__ float s_c[2 * TDD];
    __shared__ float s_te[KNB * TDD];
    __shared__ float s_sc[2 * KNB];
    __shared__ float s_at[2 * KNB];
    __shared__ float s_wt[2 * TDD];
    __shared__ int s_nb[KNB];

    const float* Wk2 = Wk_full + MEMD * MEMD;   // rows 172..271 of Wk
    const float* Wv2 = Wv_full + MEMD * MEMD;
    float t_now = __ldg(&ts[E - 1]);

    if (tid < KNB) s_nb[tid] = nbi[(size_t)n * KNB + tid];
    for (int i = tid; i < MEMD; i += blockDim.x)
        s_q[i] = g_QKV[(size_t)n * G3 + i] + g_qconst[i];
    __syncthreads();

    // c[h,t] = sum_d Wk2[t, h*DH+d] * q[h*DH+d]
    for (int j = tid; j < 2 * TDD; j += blockDim.x) {
        int hh = j / TDD, t = j - hh * TDD;
        const float* wr = Wk2 + (size_t)t * MEMD + hh * DHD;
        const float* qq = s_q + hh * DHD;
        float s = 0.f;
        for (int d = 0; d < DHD; d++) s += wr[d] * qq[d];
        s_c[j] = s;
    }
    // tenc for all neighbors
    for (int j = tid; j < KNB * TDD; j += blockDim.x) {
        int k = j / TDD, t = j - k * TDD;
        float dt = t_now - nts[(size_t)n * KNB + k];
        s_te[j] = cos_acc(dt * tw[t] + tb[t]);
    }
    __syncthreads();

    // scores: 20 (k,h) pairs, one warp per 5 pairs
    int wid = tid >> 5, lane = tid & 31;
    for (int p = wid; p < 2 * KNB; p += 4) {
        int k = p >> 1, hh = p & 1;
        const float* kr = g_QKV + (size_t)s_nb[k] * G3 + MEMD + hh * DHD;
        const float* qq = s_q + hh * DHD;
        float s = 0.f;
        for (int d = lane; d < DHD; d += 32) s += qq[d] * kr[d];
        const float* cc = s_c + hh * TDD;
        const float* te = s_te + k * TDD;
        for (int t = lane; t < TDD; t += 32) s += cc[t] * te[t];
        for (int o = 16; o; o >>= 1) s += __shfl_down_sync(0xffffffffu, s, o);
        if (lane == 0) s_sc[hh * KNB + k] = s * 0.10783277320343841f;  // 1/sqrt(86)
    }
    __syncthreads();

    if (tid < 2) {
        float mx = -1e30f;
        for (int k = 0; k < KNB; k++) mx = fmaxf(mx, s_sc[tid * KNB + k]);
        float sum = 0.f;
        for (int k = 0; k < KNB; k++) {
            float e = expf(s_sc[tid * KNB + k] - mx);
            s_at[tid * KNB + k] = e;
            sum += e;
        }
        float inv = 1.f / sum;
        for (int k = 0; k < KNB; k++) s_at[tid * KNB + k] *= inv;
    }
    __syncthreads();

    // attention-weighted tenc: wt[h,t]
    for (int j = tid; j < 2 * TDD; j += blockDim.x) {
        int hh = j / TDD, t = j - hh * TDD;
        float s = 0.f;
        for (int k = 0; k < KNB; k++) s += s_at[hh * KNB + k] * s_te[k * TDD + t];
        s_wt[j] = s;
    }
    __syncthreads();

    // agg[d] = sum_k a*hV[nb][d] + sum_t wt[h,t]*Wv2[t,d]
    for (int d = tid; d < MEMD; d += blockDim.x) {
        int hh = d / DHD;
        float s = 0.f;
        for (int k = 0; k < KNB; k++)
            s += s_at[hh * KNB + k] * g_QKV[(size_t)s_nb[k] * G3 + 2 * MEMD + d];
        const float* wv = Wv2 + d;
        const float* wt = s_wt + hh * TDD;
        for (int t = 0; t < TDD; t++) s += wt[t] * wv[(size_t)t * MEMD];
        g_agg[(size_t)n * MEMD + d] = s;
    }
}

// ---------------- deterministic final reduction + classifier ----------------
__global__ void k_reduce1(int Nn) {
    int b = blockIdx.x, c = threadIdx.x;
    if (c >= MEMD) return;
    float s = 0.f;
    for (int r = 1 + b; r < Nn; r += RB) s += g_emb[(size_t)r * MEMD + c];
    g_partial[b * MEMD + c] = s;
}

__global__ void k_final(const float* __restrict__ fc2w, const float* __restrict__ fc2b,
                        float* __restrict__ out, int Nn) {
    __shared__ float tm[MEMD];
    int c = threadIdx.x;
    if (c < MEMD) {
        float s = 0.f;
        for (int b = 0; b < RB; b++) s += g_partial[b * MEMD + c];
        tm[c] = tanhf(s / (float)(Nn - 1));
    }
    __syncthreads();
    if (c == 0) {
        float l0 = fc2b[0], l1 = fc2b[1];
        for (int i = 0; i < MEMD; i++) {
            l0 += tm[i] * fc2w[i * 2 + 0];
            l1 += tm[i] * fc2w[i * 2 + 1];
        }
        float mx = fmaxf(l0, l1);
        float e0 = expf(l0 - mx), e1 = expf(l1 - mx);
        float inv = 1.f / (e0 + e1);
        out[0] = e0 * inv;
        out[1] = e1 * inv;
    }
}

// ---------------- host orchestration ----------------
extern "C" void kernel_launch(void* const* d_in, const int* in_sizes, int n_in,
                              void* d_out, int out_size) {
    const float* node_features = (const float*)d_in[0];
    const float* memory        = (const float*)d_in[1];
    const float* last_update   = (const float*)d_in[2];
    const float* timestamps    = (const float*)d_in[3];
    const float* edge_features = (const float*)d_in[4];
    const float* neighbor_ts   = (const float*)d_in[5];
    const float* time_w        = (const float*)d_in[6];
    const float* time_b        = (const float*)d_in[7];
    const float* gru_Wi        = (const float*)d_in[8];
    const float* gru_Wh        = (const float*)d_in[9];
    const float* gru_bi        = (const float*)d_in[10];
    const float* gru_bh        = (const float*)d_in[11];
    const float* Wq            = (const float*)d_in[12];
    const float* Wk            = (const float*)d_in[13];
    const float* Wv            = (const float*)d_in[14];
    const float* W1            = (const float*)d_in[15];
    const float* b1            = (const float*)d_in[16];
    const float* W2            = (const float*)d_in[17];
    const float* b2            = (const float*)d_in[18];
    const float* fc2_w         = (const float*)d_in[19];
    const float* fc2_b         = (const float*)d_in[20];
    const int*   sources       = (const int*)d_in[21];
    const int*   destinations  = (const int*)d_in[22];
    const int*   neighbor_idx  = (const int*)d_in[23];

    int N = in_sizes[0] / FEATD;
    int E = in_sizes[3];

    float *pM, *pGI, *pGH, *ph, *pQKV, *pAgg, *pT1, *pEmb, *pWiT, *pWhT, *pBqkv;
    cudaGetSymbolAddress((void**)&pM,    g_M);
    cudaGetSymbolAddress((void**)&pGI,   g_GI);
    cudaGetSymbolAddress((void**)&pGH,   g_GH);
    cudaGetSymbolAddress((void**)&ph,    g_h);
    cudaGetSymbolAddress((void**)&pQKV,  g_QKV);
    cudaGetSymbolAddress((void**)&pAgg,  g_agg);
    cudaGetSymbolAddress((void**)&pT1,   g_T1);
    cudaGetSymbolAddress((void**)&pEmb,  g_emb);
    cudaGetSymbolAddress((void**)&pWiT,  g_WiT);
    cudaGetSymbolAddress((void**)&pWhT,  g_WhT);
    cudaGetSymbolAddress((void**)&pBqkv, g_Bqkv);

    // prep
    k_init<<<(N + 255) / 256, 256>>>(N);
    k_scatter<<<(E + 255) / 256, 256>>>(sources, destinations, E);
    k_prep_wit<<<(MSGD * G3 + 255) / 256, 256>>>(gru_Wi);
    k_prep_wht<<<(MEMD * G3 + 255) / 256, 256>>>(gru_Wh);
    k_prep_bqkv<<<(MEMD * G3 + 255) / 256, 256>>>(Wq, Wk, Wv);
    k_prep_qconst<<<1, 192>>>(Wq, time_b);

    // messages -> GRU
    k_build_m<<<N, 128>>>(memory, last_update, timestamps, edge_features,
                          time_w, time_b, sources, destinations, N, E);
    {
        dim3 g((G3 + BN - 1) / BN, (N + BM - 1) / BM);
        k_gemm<<<g, 256>>>(pM, pWiT, gru_bi, pGI, N, G3, MSGD, 0, 0);
        k_gemm<<<g, 256>>>(memory, pWhT, gru_bh, pGH, N, G3, MEMD, 0, 0);
    }
    k_gate<<<(N * MEMD + 255) / 256, 256>>>(memory, node_features, N);

    // QKV projection
    {
        dim3 g((G3 + BN - 1) / BN, (N + BM - 1) / BM);
        k_gemm<<<g, 256>>>(ph, pBqkv, nullptr, pQKV, N, G3, MEMD, 0, 0);
    }

    // attention
    k_attn<<<N, 128>>>(Wk, Wv, neighbor_idx, neighbor_ts, time_w, time_b,
                       timestamps, N, E);

    // MLP: T1 = relu(h@W1a + agg@W1b + b1); emb = T1@W2 + b2
    {
        dim3 g((MEMD + BN - 1) / BN, (N + BM - 1) / BM);
        k_gemm<<<g, 256>>>(ph, W1, b1, pT1, N, MEMD, MEMD, 0, 0);
        k_gemm<<<g, 256>>>(pAgg, W1 + MEMD * MEMD, nullptr, pT1, N, MEMD, MEMD, 1, 1);
        k_gemm<<<g, 256>>>(pT1, W2, b2, pEmb, N, MEMD, MEMD, 0, 0);
    }

    // classifier head
    k_reduce1<<<RB, 192>>>(N);
    k_final<<<1, 192>>>(fc2_w, fc2_b, (float*)d_out, N);
}

// round 5
// speedup vs baseline: 1.0729x; 1.0729x over previous
#include <cuda_runtime.h>
#include <cuda_bf16.h>
#include <mma.h>
#include <math.h>

using namespace nvcuda;

#define MEMD 172
#define FEATD 172
#define TDD 100
#define KNB 10
#define DHD 86
#define MSGD 616          // 2*MEM + FEAT + TD
#define G3 516            // 3*MEM
#define NMAX 100000
#define RB 256            // reduction partial blocks

// ---------------- scratch (static device globals) — exact round-1 layouts ----------------
__device__ int   g_lastpos[NMAX];
__device__ float g_M[(size_t)NMAX * MSGD];        // selected messages   [N,616]
__device__ float g_GI[(size_t)NMAX * G3];         // m @ WiT + bi        [N,516]
__device__ float g_GH[(size_t)NMAX * G3];         // mem @ WhT + bh      [N,516]
__device__ float g_h[(size_t)NMAX * MEMD];        // updated mem + feats [N,172]
__device__ float g_QKV[(size_t)NMAX * G3];        // h @ [Wq1|Wk1|Wv1]   [N,516]
__device__ float g_agg[(size_t)NMAX * MEMD];      // attention output    [N,172]
__device__ float g_T1[(size_t)NMAX * MEMD];       // relu(cat@W1+b1)     [N,172]
__device__ float g_emb[(size_t)NMAX * MEMD];      // embedding           [N,172]
__device__ float g_WiT[MSGD * G3];
__device__ float g_WhT[MEMD * G3];
__device__ float g_Bqkv[MEMD * G3];
__device__ float g_qconst[MEMD];
__device__ float g_partial[RB * MEMD];

// robust cos for large args (fast-math-safe): fp64 2*pi range reduction
__device__ __forceinline__ float cos_acc(float x) {
    double xd = (double)x;
    double q = rint(xd * 0.15915494309189535);      // x / (2*pi)
    float r = (float)(xd - q * 6.283185307179586);
    return cosf(r);
}

// ---------------- small prep kernels (round-1 verbatim) ----------------
__global__ void k_init(int N) {
    int i = blockIdx.x * blockDim.x + threadIdx.x;
    if (i < N) g_lastpos[i] = -1;
}

__global__ void k_scatter(const int* __restrict__ src, const int* __restrict__ dst, int E) {
    int e = blockIdx.x * blockDim.x + threadIdx.x;
    if (e < E) {
        atomicMax(&g_lastpos[src[e]], e);
        atomicMax(&g_lastpos[dst[e]], E + e);
    }
}

__global__ void k_prep_wit(const float* __restrict__ Wi) {   // WiT[k*516+j] = Wi[j*616+k]
    int idx = blockIdx.x * blockDim.x + threadIdx.x;
    if (idx < MSGD * G3) {
        int k = idx / G3, j = idx - k * G3;
        g_WiT[idx] = Wi[j * MSGD + k];
    }
}

__global__ void k_prep_wht(const float* __restrict__ Wh) {   // WhT[k*516+j] = Wh[j*172+k]
    int idx = blockIdx.x * blockDim.x + threadIdx.x;
    if (idx < MEMD * G3) {
        int k = idx / G3, j = idx - k * G3;
        g_WhT[idx] = Wh[j * MEMD + k];
    }
}

__global__ void k_prep_bqkv(const float* __restrict__ Wq, const float* __restrict__ Wk,
                            const float* __restrict__ Wv) {
    int idx = blockIdx.x * blockDim.x + threadIdx.x;
    if (idx < MEMD * G3) {
        int k = idx / G3, j = idx - k * G3;
        int sel = j / MEMD, jj = j - sel * MEMD;
        const float* W = (sel == 0) ? Wq : ((sel == 1) ? Wk : Wv);
        g_Bqkv[idx] = W[k * MEMD + jj];
    }
}

__global__ void k_prep_qconst(const float* __restrict__ Wq, const float* __restrict__ tb) {
    int j = threadIdx.x;
    if (j < MEMD) {
        float s = 0.f;
        for (int t = 0; t < TDD; t++)
            s += cos_acc(tb[t]) * Wq[(MEMD + t) * MEMD + j];
        g_qconst[j] = s;
    }
}

// ---------------- build selected message matrix [N,616] (round-1 verbatim) ----------------
__global__ void k_build_m(const float* __restrict__ mem, const float* __restrict__ lu,
                          const float* __restrict__ ts, const float* __restrict__ ef,
                          const float* __restrict__ tw, const float* __restrict__ tb,
                          const int* __restrict__ src, const int* __restrict__ dst,
                          int Nn, int E) {
    int n = blockIdx.x;
    if (n >= Nn) return;
    int tid = threadIdx.x;
    __shared__ int s_a, s_b, s_e, s_has;
    __shared__ float s_dt;
    if (tid == 0) {
        int p = g_lastpos[n];
        if (p < 0) {
            s_has = 0;
        } else {
            s_has = 1;
            int e, a, b;
            if (p < E) { e = p;     a = src[e]; b = dst[e]; }
            else       { e = p - E; a = dst[e]; b = src[e]; }
            s_e = e; s_a = a; s_b = b;
            s_dt = ts[e] - lu[a];
        }
    }
    __syncthreads();
    float* row = g_M + (size_t)n * MSGD;
    if (!s_has) {
        for (int i = tid; i < MSGD; i += blockDim.x) row[i] = 0.f;
        return;
    }
    int a = s_a, b = s_b, e = s_e;
    float dt = s_dt;
    for (int i = tid; i < MSGD; i += blockDim.x) {
        float v;
        if (i < MEMD)            v = mem[(size_t)a * MEMD + i];
        else if (i < 2 * MEMD)   v = mem[(size_t)b * MEMD + (i - MEMD)];
        else if (i < 2 * MEMD + FEATD) v = ef[(size_t)e * FEATD + (i - 2 * MEMD)];
        else { int t = i - (2 * MEMD + FEATD); v = cos_acc(dt * tw[t] + tb[t]); }
        row[i] = v;
    }
}

// ---------------- tensor-core GEMM with fp32 I/O: C = A[M,K] @ B[K,N] (+bias,+accum,+relu)
// A, B, C are fp32 in their natural round-1 layouts. Internally: split to bf16 hi/lo
// in smem, 3-product wmma (AhBh + AhBl + AlBh), fp32 accum. 128x128 block tile,
// BK=32, 8 warps (2x4), warp tile 64x32. Epilogue staged through smem with full
// M/N guards and round-1 semantics (bias -> accum -> relu).
#define GBK 32
#define APADS 40     // smem k-stride for A hi/lo tiles ([128][APADS])
#define BPADS 136    // smem n-stride for B hi/lo tiles ([32][BPADS])
#define CPADS 132    // smem n-stride for epilogue tile ([64][CPADS])
#define SRAW_BYTES (128*APADS*2*2 + GBK*BPADS*2*2)   // 37888; Cs needs 64*132*4=33792 <= this

__global__ __launch_bounds__(256) void k_gemm3(
        const float* __restrict__ A, const float* __restrict__ B,
        const float* __restrict__ bias, float* __restrict__ C,
        int M, int N, int K, int accum, int relu) {
    __shared__ __align__(16) unsigned char sraw[SRAW_BYTES];
    __nv_bfloat16* Ah = (__nv_bfloat16*)sraw;              // [128][APADS]
    __nv_bfloat16* Al = Ah + 128 * APADS;
    __nv_bfloat16* Bh = Al + 128 * APADS;                  // [GBK][BPADS]
    __nv_bfloat16* Bl = Bh + GBK * BPADS;
    float* Cs = (float*)sraw;                              // epilogue overlay [64][CPADS]

    int tid = threadIdx.x;
    int w = tid >> 5;
    int wm = w >> 2, wn = w & 3;
    int row0 = blockIdx.y * 128;
    int col0 = blockIdx.x * 128;

    wmma::fragment<wmma::accumulator, 16, 16, 16, float> acc[4][2];
#pragma unroll
    for (int i = 0; i < 4; i++)
#pragma unroll
        for (int j = 0; j < 2; j++) wmma::fill_fragment(acc[i][j], 0.f);

    int nk = (K + GBK - 1) / GBK;
    for (int kc = 0; kc < nk; kc++) {
        int k0 = kc * GBK;
        // ---- load A tile 128x32 (fp32) -> split hi/lo into smem ----
        {
            int r = tid >> 1, kh = (tid & 1) * 16;   // each thread: 16 k-elems = 8 float2
            int gr = row0 + r;
            const float* Arow = A + (size_t)gr * K + k0 + kh;
#pragma unroll
            for (int u = 0; u < 8; u++) {
                int gk = k0 + kh + 2 * u;
                float2 v = make_float2(0.f, 0.f);
                if (gr < M && gk < K) v = *(const float2*)(Arow + 2 * u);  // K even => gk+1<K
                __nv_bfloat16 hx = __float2bfloat16(v.x);
                __nv_bfloat16 hy = __float2bfloat16(v.y);
                int o = r * APADS + kh + 2 * u;
                Ah[o] = hx;     Ah[o + 1] = hy;
                Al[o] = __float2bfloat16(v.x - __bfloat162float(hx));
                Al[o + 1] = __float2bfloat16(v.y - __bfloat162float(hy));
            }
        }
        // ---- load B tile 32x128 (fp32, row-major [K][N]) -> split hi/lo ----
        {
            int kk = tid >> 3, ns = (tid & 7) * 16;  // each thread: 16 n-elems = 8 float2
            int gk = k0 + kk;
            const float* Brow = B + (size_t)gk * N + col0 + ns;
#pragma unroll
            for (int u = 0; u < 8; u++) {
                int gc = col0 + ns + 2 * u;
                float2 v = make_float2(0.f, 0.f);
                if (gk < K && gc < N) v = *(const float2*)(Brow + 2 * u);  // N even => gc+1<N
                __nv_bfloat16 hx = __float2bfloat16(v.x);
                __nv_bfloat16 hy = __float2bfloat16(v.y);
                int o = kk * BPADS + ns + 2 * u;
                Bh[o] = hx;     Bh[o + 1] = hy;
                Bl[o] = __float2bfloat16(v.x - __bfloat162float(hx));
                Bl[o + 1] = __float2bfloat16(v.y - __bfloat162float(hy));
            }
        }
        __syncthreads();
        // ---- mma: 3-product ----
#pragma unroll
        for (int ks = 0; ks < GBK; ks += 16) {
            wmma::fragment<wmma::matrix_b, 16, 16, 16, __nv_bfloat16, wmma::row_major> bh[2], bl[2];
            wmma::load_matrix_sync(bh[0], Bh + ks * BPADS + wn * 32,      BPADS);
            wmma::load_matrix_sync(bh[1], Bh + ks * BPADS + wn * 32 + 16, BPADS);
            wmma::load_matrix_sync(bl[0], Bl + ks * BPADS + wn * 32,      BPADS);
            wmma::load_matrix_sync(bl[1], Bl + ks * BPADS + wn * 32 + 16, BPADS);
#pragma unroll
            for (int im = 0; im < 4; im++) {
                wmma::fragment<wmma::matrix_a, 16, 16, 16, __nv_bfloat16, wmma::row_major> ah, al;
                wmma::load_matrix_sync(ah, Ah + (wm * 64 + im * 16) * APADS + ks, APADS);
                wmma::load_matrix_sync(al, Al + (wm * 64 + im * 16) * APADS + ks, APADS);
#pragma unroll
                for (int j = 0; j < 2; j++) {
                    wmma::mma_sync(acc[im][j], ah, bh[j], acc[im][j]);
                    wmma::mma_sync(acc[im][j], ah, bl[j], acc[im][j]);
                    wmma::mma_sync(acc[im][j], al, bh[j], acc[im][j]);
                }
            }
        }
        __syncthreads();
    }

    // ---- epilogue: two 64-row phases staged via smem, full guards ----
    for (int ph = 0; ph < 2; ph++) {
        if (wm == ph) {
#pragma unroll
            for (int im = 0; im < 4; im++)
#pragma unroll
                for (int j = 0; j < 2; j++)
                    wmma::store_matrix_sync(Cs + (im * 16) * CPADS + wn * 32 + j * 16,
                                            acc[im][j], CPADS, wmma::mem_row_major);
        }
        __syncthreads();
        for (int e = tid; e < 64 * 128; e += 256) {
            int rr = e >> 7, cc = e & 127;
            int gr = row0 + ph * 64 + rr, gc = col0 + cc;
            if (gr < M && gc < N) {
                float v = Cs[rr * CPADS + cc];
                if (bias) v += bias[gc];
                size_t ix = (size_t)gr * N + gc;
                if (accum) v += C[ix];
                if (relu) v = fmaxf(v, 0.f);
                C[ix] = v;
            }
        }
        __syncthreads();
    }
}

// ---------------- GRU gating + h = mem_upd + node_features (round-1 verbatim) ----------------
__global__ void k_gate(const float* __restrict__ mem, const float* __restrict__ nf, int Nn) {
    int idx = blockIdx.x * blockDim.x + threadIdx.x;
    if (idx >= Nn * MEMD) return;
    int n = idx / MEMD, d = idx - n * MEMD;
    float mv = mem[idx];
    float hv;
    if (g_lastpos[n] >= 0) {
        const float* gi = g_GI + (size_t)n * G3;
        const float* gh = g_GH + (size_t)n * G3;
        float r = 1.f / (1.f + expf(-(gi[d] + gh[d])));
        float z = 1.f / (1.f + expf(-(gi[MEMD + d] + gh[MEMD + d])));
        float g = tanhf(gi[2 * MEMD + d] + r * gh[2 * MEMD + d]);
        hv = (1.f - z) * g + z * mv;
    } else {
        hv = mv;
    }
    g_h[idx] = hv + nf[idx];
}

// ---------------- temporal attention (round-1 verbatim) ----------------
__global__ void k_attn(const float* __restrict__ Wk_full, const float* __restrict__ Wv_full,
                       const int* __restrict__ nbi, const float* __restrict__ nts,
                       const float* __restrict__ tw, const float* __restrict__ tb,
                       const float* __restrict__ ts, int Nn, int E) {
    int n = blockIdx.x;
    if (n >= Nn) return;
    int tid = threadIdx.x;
    __shared__ float s_q[MEMD];
    __shared__ float s_c[2 * TDD];
    __shared__ float s_te[KNB * TDD];
    __shared__ float s_sc[2 * KNB];
    __shared__ float s_at[2 * KNB];
    __shared__ float s_wt[2 * TDD];
    __shared__ int s_nb[KNB];

    const float* Wk2 = Wk_full + MEMD * MEMD;
    const float* Wv2 = Wv_full + MEMD * MEMD;
    float t_now = __ldg(&ts[E - 1]);

    if (tid < KNB) s_nb[tid] = nbi[(size_t)n * KNB + tid];
    for (int i = tid; i < MEMD; i += blockDim.x)
        s_q[i] = g_QKV[(size_t)n * G3 + i] + g_qconst[i];
    __syncthreads();

    for (int j = tid; j < 2 * TDD; j += blockDim.x) {
        int hh = j / TDD, t = j - hh * TDD;
        const float* wr = Wk2 + (size_t)t * MEMD + hh * DHD;
        const float* qq = s_q + hh * DHD;
        float s = 0.f;
        for (int d = 0; d < DHD; d++) s += wr[d] * qq[d];
        s_c[j] = s;
    }
    for (int j = tid; j < KNB * TDD; j += blockDim.x) {
        int k = j / TDD, t = j - k * TDD;
        float dt = t_now - nts[(size_t)n * KNB + k];
        s_te[j] = cos_acc(dt * tw[t] + tb[t]);
    }
    __syncthreads();

    int wid = tid >> 5, lane = tid & 31;
    for (int p = wid; p < 2 * KNB; p += 4) {
        int k = p >> 1, hh = p & 1;
        const float* kr = g_QKV + (size_t)s_nb[k] * G3 + MEMD + hh * DHD;
        const float* qq = s_q + hh * DHD;
        float s = 0.f;
        for (int d = lane; d < DHD; d += 32) s += qq[d] * kr[d];
        const float* cc = s_c + hh * TDD;
        const float* te = s_te + k * TDD;
        for (int t = lane; t < TDD; t += 32) s += cc[t] * te[t];
        for (int o = 16; o; o >>= 1) s += __shfl_down_sync(0xffffffffu, s, o);
        if (lane == 0) s_sc[hh * KNB + k] = s * 0.10783277320343841f;  // 1/sqrt(86)
    }
    __syncthreads();

    if (tid < 2) {
        float mx = -1e30f;
        for (int k = 0; k < KNB; k++) mx = fmaxf(mx, s_sc[tid * KNB + k]);
        float sum = 0.f;
        for (int k = 0; k < KNB; k++) {
            float e = expf(s_sc[tid * KNB + k] - mx);
            s_at[tid * KNB + k] = e;
            sum += e;
        }
        float inv = 1.f / sum;
        for (int k = 0; k < KNB; k++) s_at[tid * KNB + k] *= inv;
    }
    __syncthreads();

    for (int j = tid; j < 2 * TDD; j += blockDim.x) {
        int hh = j / TDD, t = j - hh * TDD;
        float s = 0.f;
        for (int k = 0; k < KNB; k++) s += s_at[hh * KNB + k] * s_te[k * TDD + t];
        s_wt[j] = s;
    }
    __syncthreads();

    for (int d = tid; d < MEMD; d += blockDim.x) {
        int hh = d / DHD;
        float s = 0.f;
        for (int k = 0; k < KNB; k++)
            s += s_at[hh * KNB + k] * g_QKV[(size_t)s_nb[k] * G3 + 2 * MEMD + d];
        const float* wv = Wv2 + d;
        const float* wt = s_wt + hh * TDD;
        for (int t = 0; t < TDD; t++) s += wt[t] * wv[(size_t)t * MEMD];
        g_agg[(size_t)n * MEMD + d] = s;
    }
}

// ---------------- deterministic final reduction + classifier (round-1 verbatim) ----------------
__global__ void k_reduce1(int Nn) {
    int b = blockIdx.x, c = threadIdx.x;
    if (c >= MEMD) return;
    float s = 0.f;
    for (int r = 1 + b; r < Nn; r += RB) s += g_emb[(size_t)r * MEMD + c];
    g_partial[b * MEMD + c] = s;
}

__global__ void k_final(const float* __restrict__ fc2w, const float* __restrict__ fc2b,
                        float* __restrict__ out, int Nn) {
    __shared__ float tm[MEMD];
    int c = threadIdx.x;
    if (c < MEMD) {
        float s = 0.f;
        for (int b = 0; b < RB; b++) s += g_partial[b * MEMD + c];
        tm[c] = tanhf(s / (float)(Nn - 1));
    }
    __syncthreads();
    if (c == 0) {
        float l0 = fc2b[0], l1 = fc2b[1];
        for (int i = 0; i < MEMD; i++) {
            l0 += tm[i] * fc2w[i * 2 + 0];
            l1 += tm[i] * fc2w[i * 2 + 1];
        }
        float mx = fmaxf(l0, l1);
        float e0 = expf(l0 - mx), e1 = expf(l1 - mx);
        float inv = 1.f / (e0 + e1);
        out[0] = e0 * inv;
        out[1] = e1 * inv;
    }
}

// ---------------- host orchestration (round-1 structure; only GEMM kernel + grids changed) ----
extern "C" void kernel_launch(void* const* d_in, const int* in_sizes, int n_in,
                              void* d_out, int out_size) {
    const float* node_features = (const float*)d_in[0];
    const float* memory        = (const float*)d_in[1];
    const float* last_update   = (const float*)d_in[2];
    const float* timestamps    = (const float*)d_in[3];
    const float* edge_features = (const float*)d_in[4];
    const float* neighbor_ts   = (const float*)d_in[5];
    const float* time_w        = (const float*)d_in[6];
    const float* time_b        = (const float*)d_in[7];
    const float* gru_Wi        = (const float*)d_in[8];
    const float* gru_Wh        = (const float*)d_in[9];
    const float* gru_bi        = (const float*)d_in[10];
    const float* gru_bh        = (const float*)d_in[11];
    const float* Wq            = (const float*)d_in[12];
    const float* Wk            = (const float*)d_in[13];
    const float* Wv            = (const float*)d_in[14];
    const float* W1            = (const float*)d_in[15];
    const float* b1            = (const float*)d_in[16];
    const float* W2            = (const float*)d_in[17];
    const float* b2            = (const float*)d_in[18];
    const float* fc2_w         = (const float*)d_in[19];
    const float* fc2_b         = (const float*)d_in[20];
    const int*   sources       = (const int*)d_in[21];
    const int*   destinations  = (const int*)d_in[22];
    const int*   neighbor_idx  = (const int*)d_in[23];

    int N = in_sizes[0] / FEATD;
    int E = in_sizes[3];

    float *pM, *pGI, *pGH, *ph, *pQKV, *pAgg, *pT1, *pEmb, *pWiT, *pWhT, *pBqkv;
    cudaGetSymbolAddress((void**)&pM,    g_M);
    cudaGetSymbolAddress((void**)&pGI,   g_GI);
    cudaGetSymbolAddress((void**)&pGH,   g_GH);
    cudaGetSymbolAddress((void**)&ph,    g_h);
    cudaGetSymbolAddress((void**)&pQKV,  g_QKV);
    cudaGetSymbolAddress((void**)&pAgg,  g_agg);
    cudaGetSymbolAddress((void**)&pT1,   g_T1);
    cudaGetSymbolAddress((void**)&pEmb,  g_emb);
    cudaGetSymbolAddress((void**)&pWiT,  g_WiT);
    cudaGetSymbolAddress((void**)&pWhT,  g_WhT);
    cudaGetSymbolAddress((void**)&pBqkv, g_Bqkv);

    // prep
    k_init<<<(N + 255) / 256, 256>>>(N);
    k_scatter<<<(E + 255) / 256, 256>>>(sources, destinations, E);
    k_prep_wit<<<(MSGD * G3 + 255) / 256, 256>>>(gru_Wi);
    k_prep_wht<<<(MEMD * G3 + 255) / 256, 256>>>(gru_Wh);
    k_prep_bqkv<<<(MEMD * G3 + 255) / 256, 256>>>(Wq, Wk, Wv);
    k_prep_qconst<<<1, 192>>>(Wq, time_b);

    // messages -> GRU
    k_build_m<<<N, 128>>>(memory, last_update, timestamps, edge_features,
                          time_w, time_b, sources, destinations, N, E);
    {
        dim3 g((G3 + 127) / 128, (N + 127) / 128);
        k_gemm3<<<g, 256>>>(pM, pWiT, gru_bi, pGI, N, G3, MSGD, 0, 0);
        k_gemm3<<<g, 256>>>(memory, pWhT, gru_bh, pGH, N, G3, MEMD, 0, 0);
    }
    k_gate<<<(N * MEMD + 255) / 256, 256>>>(memory, node_features, N);

    // QKV projection
    {
        dim3 g((G3 + 127) / 128, (N + 127) / 128);
        k_gemm3<<<g, 256>>>(ph, pBqkv, nullptr, pQKV, N, G3, MEMD, 0, 0);
    }

    // attention
    k_attn<<<N, 128>>>(Wk, Wv, neighbor_idx, neighbor_ts, time_w, time_b,
                       timestamps, N, E);

    // MLP: T1 = relu(h@W1a + agg@W1b + b1); emb = T1@W2 + b2
    {
        dim3 g((MEMD + 127) / 128, (N + 127) / 128);
        k_gemm3<<<g, 256>>>(ph, W1, b1, pT1, N, MEMD, MEMD, 0, 0);
        k_gemm3<<<g, 256>>>(pAgg, W1 + MEMD * MEMD, nullptr, pT1, N, MEMD, MEMD, 1, 1);
        k_gemm3<<<g, 256>>>(pT1, W2, b2, pEmb, N, MEMD, MEMD, 0, 0);
    }

    // classifier head
    k_reduce1<<<RB, 192>>>(N);
    k_final<<<1, 192>>>(fc2_w, fc2_b, (float*)d_out, N);
}

// round 6
// speedup vs baseline: 1.1304x; 1.0536x over previous
#include <cuda_runtime.h>
#include <cuda_bf16.h>
#include <mma.h>
#include <math.h>

using namespace nvcuda;

#define MEMD 172
#define FEATD 172
#define TDD 100
#define KNB 10
#define DHD 86
#define MSGD 616          // 2*MEM + FEAT + TD
#define G3 516            // 3*MEM
#define NMAX 100000
#define NPAD 100096       // ceil(100000/128)*128 rows for A-operand buffers
#define RB 256

// padded K strides for bf16 operand buffers
#define KP_M 640          // 616 -> 640
#define KP_S 192          // 172 -> 192
// padded N strides for B operand buffers
#define NP_G 640          // 516 -> 640
#define NP_S 256          // 172 -> 256

// ---------------- device scratch ----------------
__device__ int   g_lastpos[NMAX];
// A-operand split planes (explicitly zero-padded by producers)
__device__ __nv_bfloat16 g_Mh[(size_t)NPAD * KP_M];
__device__ __nv_bfloat16 g_Ml[(size_t)NPAD * KP_M];
__device__ __nv_bfloat16 g_memh[(size_t)NPAD * KP_S];
__device__ __nv_bfloat16 g_meml[(size_t)NPAD * KP_S];
__device__ __nv_bfloat16 g_hh[(size_t)NPAD * KP_S];
__device__ __nv_bfloat16 g_hl[(size_t)NPAD * KP_S];
__device__ __nv_bfloat16 g_aggh[(size_t)NPAD * KP_S];
__device__ __nv_bfloat16 g_aggl[(size_t)NPAD * KP_S];
__device__ __nv_bfloat16 g_t1h[(size_t)NPAD * KP_S];
__device__ __nv_bfloat16 g_t1l[(size_t)NPAD * KP_S];
// B-operand split planes [Kp][Np], explicitly zero-padded
__device__ __nv_bfloat16 g_BWih[KP_M * NP_G];
__device__ __nv_bfloat16 g_BWil[KP_M * NP_G];
__device__ __nv_bfloat16 g_BWhh[KP_S * NP_G];
__device__ __nv_bfloat16 g_BWhl[KP_S * NP_G];
__device__ __nv_bfloat16 g_BQh[KP_S * NP_G];
__device__ __nv_bfloat16 g_BQl[KP_S * NP_G];
__device__ __nv_bfloat16 g_BW1ah[KP_S * NP_S];
__device__ __nv_bfloat16 g_BW1al[KP_S * NP_S];
__device__ __nv_bfloat16 g_BW1bh[KP_S * NP_S];
__device__ __nv_bfloat16 g_BW1bl[KP_S * NP_S];
__device__ __nv_bfloat16 g_BW2h[KP_S * NP_S];
__device__ __nv_bfloat16 g_BW2l[KP_S * NP_S];
// fp32 GEMM outputs (round-1 layouts, unpadded)
__device__ float g_GI[(size_t)NMAX * G3];
__device__ float g_GH[(size_t)NMAX * G3];
__device__ float g_QKV[(size_t)NMAX * G3];
__device__ float g_T1[(size_t)NMAX * MEMD];
__device__ float g_emb[(size_t)NMAX * MEMD];
__device__ float g_qconst[MEMD];
__device__ float g_partial[RB * MEMD];

// robust cos for large args (fast-math-safe): fp64 2*pi range reduction
__device__ __forceinline__ float cos_acc(float x) {
    double xd = (double)x;
    double q = rint(xd * 0.15915494309189535);
    float r = (float)(xd - q * 6.283185307179586);
    return cosf(r);
}

__device__ __forceinline__ void split2(float x, __nv_bfloat16* hi, __nv_bfloat16* lo) {
    __nv_bfloat16 h = __float2bfloat16(x);
    *hi = h;
    *lo = __float2bfloat16(x - __bfloat162float(h));
}

// ---------------- prep kernels ----------------
__global__ void k_init(int N) {
    int i = blockIdx.x * blockDim.x + threadIdx.x;
    if (i < N) g_lastpos[i] = -1;
}

__global__ void k_scatter(const int* __restrict__ src, const int* __restrict__ dst, int E) {
    int e = blockIdx.x * blockDim.x + threadIdx.x;
    if (e < E) {
        atomicMax(&g_lastpos[src[e]], e);
        atomicMax(&g_lastpos[dst[e]], E + e);
    }
}

// B_Wi[k][n] = Wi[n*616+k] (Wi is [516][616]); shape [640][640], zero pads
__global__ void k_prep_wi(const float* __restrict__ Wi) {
    int idx = blockIdx.x * blockDim.x + threadIdx.x;
    if (idx < KP_M * NP_G) {
        int k = idx / NP_G, n = idx - k * NP_G;
        float v = (k < MSGD && n < G3) ? Wi[n * MSGD + k] : 0.f;
        split2(v, &g_BWih[idx], &g_BWil[idx]);
    }
}

// B_Wh[k][n] = Wh[n*172+k]; shape [192][640]
__global__ void k_prep_wh(const float* __restrict__ Wh) {
    int idx = blockIdx.x * blockDim.x + threadIdx.x;
    if (idx < KP_S * NP_G) {
        int k = idx / NP_G, n = idx - k * NP_G;
        float v = (k < MEMD && n < G3) ? Wh[n * MEMD + k] : 0.f;
        split2(v, &g_BWhh[idx], &g_BWhl[idx]);
    }
}

// B_Q[k][n]: n in [0,516): sel=n/172 picks Wq/Wk/Wv; value = Wsel[k*172 + n%172]
__global__ void k_prep_qkv(const float* __restrict__ Wq, const float* __restrict__ Wk,
                           const float* __restrict__ Wv) {
    int idx = blockIdx.x * blockDim.x + threadIdx.x;
    if (idx < KP_S * NP_G) {
        int k = idx / NP_G, n = idx - k * NP_G;
        float v = 0.f;
        if (k < MEMD && n < G3) {
            int sel = n / MEMD, jj = n - sel * MEMD;
            const float* W = (sel == 0) ? Wq : ((sel == 1) ? Wk : Wv);
            v = W[k * MEMD + jj];
        }
        split2(v, &g_BQh[idx], &g_BQl[idx]);
    }
}

// W1 is [344][172]: B1a[k][n] = W1[k][n], B1b[k][n] = W1[172+k][n]; shapes [192][256]
__global__ void k_prep_w1(const float* __restrict__ W1) {
    int idx = blockIdx.x * blockDim.x + threadIdx.x;
    if (idx < KP_S * NP_S) {
        int k = idx / NP_S, n = idx - k * NP_S;
        float va = 0.f, vb = 0.f;
        if (k < MEMD && n < MEMD) {
            va = W1[k * MEMD + n];
            vb = W1[(MEMD + k) * MEMD + n];
        }
        split2(va, &g_BW1ah[idx], &g_BW1al[idx]);
        split2(vb, &g_BW1bh[idx], &g_BW1bl[idx]);
    }
}

__global__ void k_prep_w2(const float* __restrict__ W2) {
    int idx = blockIdx.x * blockDim.x + threadIdx.x;
    if (idx < KP_S * NP_S) {
        int k = idx / NP_S, n = idx - k * NP_S;
        float v = (k < MEMD && n < MEMD) ? W2[k * MEMD + n] : 0.f;
        split2(v, &g_BW2h[idx], &g_BW2l[idx]);
    }
}

__global__ void k_prep_qconst(const float* __restrict__ Wq, const float* __restrict__ tb) {
    int j = threadIdx.x;
    if (j < MEMD) {
        float s = 0.f;
        for (int t = 0; t < TDD; t++)
            s += cos_acc(tb[t]) * Wq[(MEMD + t) * MEMD + j];
        g_qconst[j] = s;
    }
}

// memory -> split planes [NPAD][192], zero pads
__global__ void k_memconv(const float* __restrict__ mem, int Nn) {
    int idx = blockIdx.x * blockDim.x + threadIdx.x;
    if (idx >= NPAD * KP_S) return;
    int n = idx / KP_S, d = idx - n * KP_S;
    float v = (n < Nn && d < MEMD) ? mem[(size_t)n * MEMD + d] : 0.f;
    split2(v, &g_memh[idx], &g_meml[idx]);
}

// ---------------- build selected message matrix -> split planes [NPAD][640] ----------------
__global__ void k_build_m(const float* __restrict__ mem, const float* __restrict__ lu,
                          const float* __restrict__ ts, const float* __restrict__ ef,
                          const float* __restrict__ tw, const float* __restrict__ tb,
                          const int* __restrict__ src, const int* __restrict__ dst,
                          int Nn, int E) {
    int n = blockIdx.x;
    int tid = threadIdx.x;
    __nv_bfloat16* rh = g_Mh + (size_t)n * KP_M;
    __nv_bfloat16* rl = g_Ml + (size_t)n * KP_M;
    __shared__ int s_a, s_b, s_e, s_has;
    __shared__ float s_dt;
    if (tid == 0) {
        int p = (n < Nn) ? g_lastpos[n] : -1;
        if (p < 0) {
            s_has = 0;
        } else {
            s_has = 1;
            int e, a, b;
            if (p < E) { e = p;     a = src[e]; b = dst[e]; }
            else       { e = p - E; a = dst[e]; b = src[e]; }
            s_e = e; s_a = a; s_b = b;
            s_dt = ts[e] - lu[a];
        }
    }
    __syncthreads();
    if (!s_has) {
        __nv_bfloat16 z = __float2bfloat16(0.f);
        for (int i = tid; i < KP_M; i += blockDim.x) { rh[i] = z; rl[i] = z; }
        return;
    }
    int a = s_a, b = s_b, e = s_e;
    float dt = s_dt;
    for (int i = tid; i < KP_M; i += blockDim.x) {
        float v = 0.f;
        if (i < MEMD)                  v = mem[(size_t)a * MEMD + i];
        else if (i < 2 * MEMD)         v = mem[(size_t)b * MEMD + (i - MEMD)];
        else if (i < 2 * MEMD + FEATD) v = ef[(size_t)e * FEATD + (i - 2 * MEMD)];
        else if (i < MSGD) { int t = i - (2 * MEMD + FEATD); v = cos_acc(dt * tw[t] + tb[t]); }
        split2(v, &rh[i], &rl[i]);
    }
}

// ---------------- 3-product bf16 wmma GEMM, pre-split operands ----------------
// C[M,N] (+)= A[M,Kp] @ B[Kp,Np], A/B bf16 hi+lo planes, fp32 C with round-1
// epilogue (bias -> accum -> relu) and full M/N guards via staged smem tile.
// 128x128 block, BK=32, 8 warps (2x4), warp tile 64x32.
#define GBK 32
#define APADS 40
#define BPADS 136
#define CPADS 132
#define SRAW_BYTES (128*APADS*2*2 + GBK*BPADS*2*2)   // 37888 B; Cs needs 33792 B

__global__ __launch_bounds__(256) void k_gemm3(
        const __nv_bfloat16* __restrict__ Agh, const __nv_bfloat16* __restrict__ Agl, int lda,
        const __nv_bfloat16* __restrict__ Bgh, const __nv_bfloat16* __restrict__ Bgl, int ldb,
        const float* __restrict__ bias, float* __restrict__ C,
        int M, int N, int Kp, int accum, int relu) {
    __shared__ __align__(16) unsigned char sraw[SRAW_BYTES];
    __nv_bfloat16* Ah = (__nv_bfloat16*)sraw;              // [128][APADS]
    __nv_bfloat16* Al = Ah + 128 * APADS;
    __nv_bfloat16* Bh = Al + 128 * APADS;                  // [GBK][BPADS]
    __nv_bfloat16* Bl = Bh + GBK * BPADS;
    float* Cs = (float*)sraw;

    int tid = threadIdx.x;
    int w = tid >> 5;
    int wm = w >> 2, wn = w & 3;
    int row0 = blockIdx.y * 128;
    int col0 = blockIdx.x * 128;

    wmma::fragment<wmma::accumulator, 16, 16, 16, float> acc[4][2];
#pragma unroll
    for (int i = 0; i < 4; i++)
#pragma unroll
        for (int j = 0; j < 2; j++) wmma::fill_fragment(acc[i][j], 0.f);

    // per-thread load coords (no bounds checks — operands fully padded)
    int ar = tid >> 1, akh = (tid & 1) * 16;   // A: 16 bf16 = 2x uint4
    int bk = tid >> 3, bns = (tid & 7) * 16;   // B: 16 bf16 = 2x uint4

    for (int k0 = 0; k0 < Kp; k0 += GBK) {
        {
            const uint4* sa_h = (const uint4*)(Agh + (size_t)(row0 + ar) * lda + k0 + akh);
            const uint4* sa_l = (const uint4*)(Agl + (size_t)(row0 + ar) * lda + k0 + akh);
            uint4* da_h = (uint4*)(Ah + ar * APADS + akh);
            uint4* da_l = (uint4*)(Al + ar * APADS + akh);
            da_h[0] = sa_h[0]; da_h[1] = sa_h[1];
            da_l[0] = sa_l[0]; da_l[1] = sa_l[1];
            const uint4* sb_h = (const uint4*)(Bgh + (size_t)(k0 + bk) * ldb + col0 + bns);
            const uint4* sb_l = (const uint4*)(Bgl + (size_t)(k0 + bk) * ldb + col0 + bns);
            uint4* db_h = (uint4*)(Bh + bk * BPADS + bns);
            uint4* db_l = (uint4*)(Bl + bk * BPADS + bns);
            db_h[0] = sb_h[0]; db_h[1] = sb_h[1];
            db_l[0] = sb_l[0]; db_l[1] = sb_l[1];
        }
        __syncthreads();
#pragma unroll
        for (int ks = 0; ks < GBK; ks += 16) {
            wmma::fragment<wmma::matrix_b, 16, 16, 16, __nv_bfloat16, wmma::row_major> bh[2], bl[2];
            wmma::load_matrix_sync(bh[0], Bh + ks * BPADS + wn * 32,      BPADS);
            wmma::load_matrix_sync(bh[1], Bh + ks * BPADS + wn * 32 + 16, BPADS);
            wmma::load_matrix_sync(bl[0], Bl + ks * BPADS + wn * 32,      BPADS);
            wmma::load_matrix_sync(bl[1], Bl + ks * BPADS + wn * 32 + 16, BPADS);
#pragma unroll
            for (int im = 0; im < 4; im++) {
                wmma::fragment<wmma::matrix_a, 16, 16, 16, __nv_bfloat16, wmma::row_major> ah, al;
                wmma::load_matrix_sync(ah, Ah + (wm * 64 + im * 16) * APADS + ks, APADS);
                wmma::load_matrix_sync(al, Al + (wm * 64 + im * 16) * APADS + ks, APADS);
#pragma unroll
                for (int j = 0; j < 2; j++) {
                    wmma::mma_sync(acc[im][j], ah, bh[j], acc[im][j]);
                    wmma::mma_sync(acc[im][j], ah, bl[j], acc[im][j]);
                    wmma::mma_sync(acc[im][j], al, bh[j], acc[im][j]);
                }
            }
        }
        __syncthreads();
    }

    // staged epilogue (round-1 semantics, full guards)
    for (int ph = 0; ph < 2; ph++) {
        if (wm == ph) {
#pragma unroll
            for (int im = 0; im < 4; im++)
#pragma unroll
                for (int j = 0; j < 2; j++)
                    wmma::store_matrix_sync(Cs + (im * 16) * CPADS + wn * 32 + j * 16,
                                            acc[im][j], CPADS, wmma::mem_row_major);
        }
        __syncthreads();
        for (int e = tid; e < 64 * 128; e += 256) {
            int rr = e >> 7, cc = e & 127;
            int gr = row0 + ph * 64 + rr, gc = col0 + cc;
            if (gr < M && gc < N) {
                float v = Cs[rr * CPADS + cc];
                if (bias) v += bias[gc];
                size_t ix = (size_t)gr * N + gc;
                if (accum) v += C[ix];
                if (relu) v = fmaxf(v, 0.f);
                C[ix] = v;
            }
        }
        __syncthreads();
    }
}

// ---------------- GRU gating + h = mem_upd + node_features -> split planes ----------------
__global__ void k_gate(const float* __restrict__ mem, const float* __restrict__ nf, int Nn) {
    int idx = blockIdx.x * blockDim.x + threadIdx.x;
    if (idx >= NPAD * KP_S) return;
    int n = idx / KP_S, d = idx - n * KP_S;
    float out = 0.f;
    if (n < Nn && d < MEMD) {
        size_t mi = (size_t)n * MEMD + d;
        float mv = mem[mi];
        float hv;
        if (g_lastpos[n] >= 0) {
            const float* gi = g_GI + (size_t)n * G3;
            const float* gh = g_GH + (size_t)n * G3;
            float r = 1.f / (1.f + expf(-(gi[d] + gh[d])));
            float z = 1.f / (1.f + expf(-(gi[MEMD + d] + gh[MEMD + d])));
            float g = tanhf(gi[2 * MEMD + d] + r * gh[2 * MEMD + d]);
            hv = (1.f - z) * g + z * mv;
        } else {
            hv = mv;
        }
        out = hv + nf[mi];
    }
    split2(out, &g_hh[idx], &g_hl[idx]);
}

// ---------------- temporal attention -> split agg planes ----------------
__global__ void k_attn(const float* __restrict__ Wk_full, const float* __restrict__ Wv_full,
                       const int* __restrict__ nbi, const float* __restrict__ nts,
                       const float* __restrict__ tw, const float* __restrict__ tb,
                       const float* __restrict__ ts, int Nn, int E) {
    int n = blockIdx.x;
    int tid = threadIdx.x;
    if (n >= Nn) {   // zero pad rows
        __nv_bfloat16 z = __float2bfloat16(0.f);
        for (int d = tid; d < KP_S; d += blockDim.x) {
            g_aggh[(size_t)n * KP_S + d] = z;
            g_aggl[(size_t)n * KP_S + d] = z;
        }
        return;
    }
    __shared__ float s_q[MEMD];
    __shared__ float s_c[2 * TDD];
    __shared__ float s_te[KNB * TDD];
    __shared__ float s_sc[2 * KNB];
    __shared__ float s_at[2 * KNB];
    __shared__ float s_wt[2 * TDD];
    __shared__ int s_nb[KNB];

    const float* Wk2 = Wk_full + MEMD * MEMD;
    const float* Wv2 = Wv_full + MEMD * MEMD;
    float t_now = __ldg(&ts[E - 1]);

    if (tid < KNB) s_nb[tid] = nbi[(size_t)n * KNB + tid];
    for (int i = tid; i < MEMD; i += blockDim.x)
        s_q[i] = g_QKV[(size_t)n * G3 + i] + g_qconst[i];
    __syncthreads();

    for (int j = tid; j < 2 * TDD; j += blockDim.x) {
        int hh = j / TDD, t = j - hh * TDD;
        const float* wr = Wk2 + (size_t)t * MEMD + hh * DHD;
        const float* qq = s_q + hh * DHD;
        float s = 0.f;
        for (int d = 0; d < DHD; d++) s += wr[d] * qq[d];
        s_c[j] = s;
    }
    for (int j = tid; j < KNB * TDD; j += blockDim.x) {
        int k = j / TDD, t = j - k * TDD;
        float dt = t_now - nts[(size_t)n * KNB + k];
        s_te[j] = cos_acc(dt * tw[t] + tb[t]);
    }
    __syncthreads();

    int wid = tid >> 5, lane = tid & 31;
    for (int p = wid; p < 2 * KNB; p += 4) {
        int k = p >> 1, hh = p & 1;
        const float* kr = g_QKV + (size_t)s_nb[k] * G3 + MEMD + hh * DHD;
        const float* qq = s_q + hh * DHD;
        float s = 0.f;
        for (int d = lane; d < DHD; d += 32) s += qq[d] * kr[d];
        const float* cc = s_c + hh * TDD;
        const float* te = s_te + k * TDD;
        for (int t = lane; t < TDD; t += 32) s += cc[t] * te[t];
        for (int o = 16; o; o >>= 1) s += __shfl_down_sync(0xffffffffu, s, o);
        if (lane == 0) s_sc[hh * KNB + k] = s * 0.10783277320343841f;  // 1/sqrt(86)
    }
    __syncthreads();

    if (tid < 2) {
        float mx = -1e30f;
        for (int k = 0; k < KNB; k++) mx = fmaxf(mx, s_sc[tid * KNB + k]);
        float sum = 0.f;
        for (int k = 0; k < KNB; k++) {
            float e = expf(s_sc[tid * KNB + k] - mx);
            s_at[tid * KNB + k] = e;
            sum += e;
        }
        float inv = 1.f / sum;
        for (int k = 0; k < KNB; k++) s_at[tid * KNB + k] *= inv;
    }
    __syncthreads();

    for (int j = tid; j < 2 * TDD; j += blockDim.x) {
        int hh = j / TDD, t = j - hh * TDD;
        float s = 0.f;
        for (int k = 0; k < KNB; k++) s += s_at[hh * KNB + k] * s_te[k * TDD + t];
        s_wt[j] = s;
    }
    __syncthreads();

    for (int d = tid; d < MEMD; d += blockDim.x) {
        int hh = d / DHD;
        float s = 0.f;
        for (int k = 0; k < KNB; k++)
            s += s_at[hh * KNB + k] * g_QKV[(size_t)s_nb[k] * G3 + 2 * MEMD + d];
        const float* wv = Wv2 + d;
        const float* wt = s_wt + hh * TDD;
        for (int t = 0; t < TDD; t++) s += wt[t] * wv[(size_t)t * MEMD];
        split2(s, &g_aggh[(size_t)n * KP_S + d], &g_aggl[(size_t)n * KP_S + d]);
    }
    // zero pad cols 172..191
    __nv_bfloat16 z = __float2bfloat16(0.f);
    for (int d = MEMD + tid; d < KP_S; d += blockDim.x) {
        g_aggh[(size_t)n * KP_S + d] = z;
        g_aggl[(size_t)n * KP_S + d] = z;
    }
}

// ---------------- T1 fp32 -> split planes ----------------
__global__ void k_t1split(int Nn) {
    int idx = blockIdx.x * blockDim.x + threadIdx.x;
    if (idx >= NPAD * KP_S) return;
    int n = idx / KP_S, d = idx - n * KP_S;
    float v = (n < Nn && d < MEMD) ? g_T1[(size_t)n * MEMD + d] : 0.f;
    split2(v, &g_t1h[idx], &g_t1l[idx]);
}

// ---------------- deterministic final reduction + classifier ----------------
__global__ void k_reduce1(int Nn) {
    int b = blockIdx.x, c = threadIdx.x;
    if (c >= MEMD) return;
    float s = 0.f;
    for (int r = 1 + b; r < Nn; r += RB) s += g_emb[(size_t)r * MEMD + c];
    g_partial[b * MEMD + c] = s;
}

__global__ void k_final(const float* __restrict__ fc2w, const float* __restrict__ fc2b,
                        float* __restrict__ out, int Nn) {
    __shared__ float tm[MEMD];
    int c = threadIdx.x;
    if (c < MEMD) {
        float s = 0.f;
        for (int b = 0; b < RB; b++) s += g_partial[b * MEMD + c];
        tm[c] = tanhf(s / (float)(Nn - 1));
    }
    __syncthreads();
    if (c == 0) {
        float l0 = fc2b[0], l1 = fc2b[1];
        for (int i = 0; i < MEMD; i++) {
            l0 += tm[i] * fc2w[i * 2 + 0];
            l1 += tm[i] * fc2w[i * 2 + 1];
        }
        float mx = fmaxf(l0, l1);
        float e0 = expf(l0 - mx), e1 = expf(l1 - mx);
        float inv = 1.f / (e0 + e1);
        out[0] = e0 * inv;
        out[1] = e1 * inv;
    }
}

// ---------------- host orchestration ----------------
extern "C" void kernel_launch(void* const* d_in, const int* in_sizes, int n_in,
                              void* d_out, int out_size) {
    const float* node_features = (const float*)d_in[0];
    const float* memory        = (const float*)d_in[1];
    const float* last_update   = (const float*)d_in[2];
    const float* timestamps    = (const float*)d_in[3];
    const float* edge_features = (const float*)d_in[4];
    const float* neighbor_ts   = (const float*)d_in[5];
    const float* time_w        = (const float*)d_in[6];
    const float* time_b        = (const float*)d_in[7];
    const float* gru_Wi        = (const float*)d_in[8];
    const float* gru_Wh        = (const float*)d_in[9];
    const float* Wq            = (const float*)d_in[12];
    const float* Wk            = (const float*)d_in[13];
    const float* Wv            = (const float*)d_in[14];
    const float* W1            = (const float*)d_in[15];
    const float* b1            = (const float*)d_in[16];
    const float* W2            = (const float*)d_in[17];
    const float* b2            = (const float*)d_in[18];
    const float* fc2_w         = (const float*)d_in[19];
    const float* fc2_b         = (const float*)d_in[20];
    const float* gru_bi        = (const float*)d_in[10];
    const float* gru_bh        = (const float*)d_in[11];
    const int*   sources       = (const int*)d_in[21];
    const int*   destinations  = (const int*)d_in[22];
    const int*   neighbor_idx  = (const int*)d_in[23];

    int N = in_sizes[0] / FEATD;
    int E = in_sizes[3];
    int MtRows = NPAD / 128;   // 782 row tiles (operands padded to NPAD rows)

    __nv_bfloat16 *pMh, *pMl, *pMemh, *pMeml, *pHh, *pHl, *pAh, *pAl, *pT1h, *pT1l;
    __nv_bfloat16 *pWih, *pWil, *pWhh, *pWhl, *pQh, *pQl, *pW1ah, *pW1al, *pW1bh, *pW1bl, *pW2h, *pW2l;
    float *pGI, *pGH, *pQKV, *pT1, *pEmb;
    cudaGetSymbolAddress((void**)&pMh,   g_Mh);
    cudaGetSymbolAddress((void**)&pMl,   g_Ml);
    cudaGetSymbolAddress((void**)&pMemh, g_memh);
    cudaGetSymbolAddress((void**)&pMeml, g_meml);
    cudaGetSymbolAddress((void**)&pHh,   g_hh);
    cudaGetSymbolAddress((void**)&pHl,   g_hl);
    cudaGetSymbolAddress((void**)&pAh,   g_aggh);
    cudaGetSymbolAddress((void**)&pAl,   g_aggl);
    cudaGetSymbolAddress((void**)&pT1h,  g_t1h);
    cudaGetSymbolAddress((void**)&pT1l,  g_t1l);
    cudaGetSymbolAddress((void**)&pWih,  g_BWih);
    cudaGetSymbolAddress((void**)&pWil,  g_BWil);
    cudaGetSymbolAddress((void**)&pWhh,  g_BWhh);
    cudaGetSymbolAddress((void**)&pWhl,  g_BWhl);
    cudaGetSymbolAddress((void**)&pQh,   g_BQh);
    cudaGetSymbolAddress((void**)&pQl,   g_BQl);
    cudaGetSymbolAddress((void**)&pW1ah, g_BW1ah);
    cudaGetSymbolAddress((void**)&pW1al, g_BW1al);
    cudaGetSymbolAddress((void**)&pW1bh, g_BW1bh);
    cudaGetSymbolAddress((void**)&pW1bl, g_BW1bl);
    cudaGetSymbolAddress((void**)&pW2h,  g_BW2h);
    cudaGetSymbolAddress((void**)&pW2l,  g_BW2l);
    cudaGetSymbolAddress((void**)&pGI,   g_GI);
    cudaGetSymbolAddress((void**)&pGH,   g_GH);
    cudaGetSymbolAddress((void**)&pQKV,  g_QKV);
    cudaGetSymbolAddress((void**)&pT1,   g_T1);
    cudaGetSymbolAddress((void**)&pEmb,  g_emb);

    // launches 0..4 (GI GEMM lands at index 5 for ncu -s 5)
    k_init<<<(N + 255) / 256, 256>>>(N);
    k_scatter<<<(E + 255) / 256, 256>>>(sources, destinations, E);
    k_prep_wi<<<(KP_M * NP_G + 255) / 256, 256>>>(gru_Wi);
    k_build_m<<<NPAD, 128>>>(memory, last_update, timestamps, edge_features,
                             time_w, time_b, sources, destinations, N, E);
    k_memconv<<<(NPAD * KP_S + 255) / 256, 256>>>(memory, N);

    // GI = M @ WiT + bi   (launch index 5 — profiled)
    k_gemm3<<<dim3(5, MtRows), 256>>>(pMh, pMl, KP_M, pWih, pWil, NP_G,
                                      gru_bi, pGI, N, G3, KP_M, 0, 0);
    k_prep_wh<<<(KP_S * NP_G + 255) / 256, 256>>>(gru_Wh);
    k_gemm3<<<dim3(5, MtRows), 256>>>(pMemh, pMeml, KP_S, pWhh, pWhl, NP_G,
                                      gru_bh, pGH, N, G3, KP_S, 0, 0);
    k_gate<<<(NPAD * KP_S + 255) / 256, 256>>>(memory, node_features, N);

    // QKV = h @ Bqkv
    k_prep_qkv<<<(KP_S * NP_G + 255) / 256, 256>>>(Wq, Wk, Wv);
    k_gemm3<<<dim3(5, MtRows), 256>>>(pHh, pHl, KP_S, pQh, pQl, NP_G,
                                      nullptr, pQKV, N, G3, KP_S, 0, 0);

    // attention
    k_prep_qconst<<<1, 192>>>(Wq, time_b);
    k_attn<<<NPAD, 128>>>(Wk, Wv, neighbor_idx, neighbor_ts, time_w, time_b,
                          timestamps, N, E);

    // MLP
    k_prep_w1<<<(KP_S * NP_S + 255) / 256, 256>>>(W1);
    k_prep_w2<<<(KP_S * NP_S + 255) / 256, 256>>>(W2);
    k_gemm3<<<dim3(2, MtRows), 256>>>(pHh, pHl, KP_S, pW1ah, pW1al, NP_S,
                                      b1, pT1, N, MEMD, KP_S, 0, 0);
    k_gemm3<<<dim3(2, MtRows), 256>>>(pAh, pAl, KP_S, pW1bh, pW1bl, NP_S,
                                      nullptr, pT1, N, MEMD, KP_S, 1, 1);
    k_t1split<<<(NPAD * KP_S + 255) / 256, 256>>>(N);
    k_gemm3<<<dim3(2, MtRows), 256>>>(pT1h, pT1l, KP_S, pW2h, pW2l, NP_S,
                                      b2, pEmb, N, MEMD, KP_S, 0, 0);

    // classifier head
    k_reduce1<<<RB, 192>>>(N);
    k_final<<<1, 192>>>(fc2_w, fc2_b, (float*)d_out, N);
}

// round 7
// speedup vs baseline: 1.1929x; 1.0553x over previous
#include <cuda_runtime.h>
#include <cuda_bf16.h>
#include <mma.h>
#include <math.h>

using namespace nvcuda;

#define MEMD 172
#define FEATD 172
#define TDD 100
#define KNB 10
#define DHD 86
#define MSGD 616          // 2*MEM + FEAT + TD
#define G3 516            // 3*MEM
#define NMAX 100000
#define NPAD 100096       // ceil(100000/128)*128 rows for A-operand buffers
#define RB 256

// padded K strides for bf16 operand buffers
#define KP_M 640          // 616 -> 640
#define KP_S 192          // 172 -> 192
// padded N strides for B operand buffers
#define NP_G 640          // 516 -> 640
#define NP_S 256          // 172 -> 256

// ---------------- device scratch ----------------
__device__ int   g_lastpos[NMAX];
// A-operand split planes (explicitly zero-padded by producers)
__device__ __nv_bfloat16 g_Mh[(size_t)NPAD * KP_M];
__device__ __nv_bfloat16 g_Ml[(size_t)NPAD * KP_M];
__device__ __nv_bfloat16 g_memh[(size_t)NPAD * KP_S];
__device__ __nv_bfloat16 g_meml[(size_t)NPAD * KP_S];
__device__ __nv_bfloat16 g_hh[(size_t)NPAD * KP_S];
__device__ __nv_bfloat16 g_hl[(size_t)NPAD * KP_S];
__device__ __nv_bfloat16 g_aggh[(size_t)NPAD * KP_S];
__device__ __nv_bfloat16 g_aggl[(size_t)NPAD * KP_S];
__device__ __nv_bfloat16 g_t1h[(size_t)NPAD * KP_S];
__device__ __nv_bfloat16 g_t1l[(size_t)NPAD * KP_S];
// B-operand split planes [Kp][Np], explicitly zero-padded
__device__ __nv_bfloat16 g_BWih[KP_M * NP_G];
__device__ __nv_bfloat16 g_BWil[KP_M * NP_G];
__device__ __nv_bfloat16 g_BWhh[KP_S * NP_G];
__device__ __nv_bfloat16 g_BWhl[KP_S * NP_G];
__device__ __nv_bfloat16 g_BQh[KP_S * NP_G];
__device__ __nv_bfloat16 g_BQl[KP_S * NP_G];
__device__ __nv_bfloat16 g_BW1ah[KP_S * NP_S];
__device__ __nv_bfloat16 g_BW1al[KP_S * NP_S];
__device__ __nv_bfloat16 g_BW1bh[KP_S * NP_S];
__device__ __nv_bfloat16 g_BW1bl[KP_S * NP_S];
__device__ __nv_bfloat16 g_BW2h[KP_S * NP_S];
__device__ __nv_bfloat16 g_BW2l[KP_S * NP_S];
// fp32 GEMM outputs (round-1 layouts, unpadded)
__device__ float g_GI[(size_t)NMAX * G3];
__device__ float g_GH[(size_t)NMAX * G3];
__device__ float g_QKV[(size_t)NMAX * G3];
__device__ float g_T1[(size_t)NMAX * MEMD];
__device__ float g_emb[(size_t)NMAX * MEMD];
__device__ float g_qconst[MEMD];
__device__ float g_partial[RB * MEMD];

// robust cos for large args (fast-math-safe): fp64 2*pi range reduction
__device__ __forceinline__ float cos_acc(float x) {
    double xd = (double)x;
    double q = rint(xd * 0.15915494309189535);
    float r = (float)(xd - q * 6.283185307179586);
    return cosf(r);
}

__device__ __forceinline__ void split2(float x, __nv_bfloat16* hi, __nv_bfloat16* lo) {
    __nv_bfloat16 h = __float2bfloat16(x);
    *hi = h;
    *lo = __float2bfloat16(x - __bfloat162float(h));
}

// ---------------- prep kernels ----------------
__global__ void k_init(int N) {
    int i = blockIdx.x * blockDim.x + threadIdx.x;
    if (i < N) g_lastpos[i] = -1;
}

__global__ void k_scatter(const int* __restrict__ src, const int* __restrict__ dst, int E) {
    int e = blockIdx.x * blockDim.x + threadIdx.x;
    if (e < E) {
        atomicMax(&g_lastpos[src[e]], e);
        atomicMax(&g_lastpos[dst[e]], E + e);
    }
}

// B_Wi[k][n] = Wi[n*616+k] (Wi is [516][616]); shape [640][640], zero pads
__global__ void k_prep_wi(const float* __restrict__ Wi) {
    int idx = blockIdx.x * blockDim.x + threadIdx.x;
    if (idx < KP_M * NP_G) {
        int k = idx / NP_G, n = idx - k * NP_G;
        float v = (k < MSGD && n < G3) ? Wi[n * MSGD + k] : 0.f;
        split2(v, &g_BWih[idx], &g_BWil[idx]);
    }
}

// B_Wh[k][n] = Wh[n*172+k]; shape [192][640]
__global__ void k_prep_wh(const float* __restrict__ Wh) {
    int idx = blockIdx.x * blockDim.x + threadIdx.x;
    if (idx < KP_S * NP_G) {
        int k = idx / NP_G, n = idx - k * NP_G;
        float v = (k < MEMD && n < G3) ? Wh[n * MEMD + k] : 0.f;
        split2(v, &g_BWhh[idx], &g_BWhl[idx]);
    }
}

// B_Q[k][n]: n in [0,516): sel=n/172 picks Wq/Wk/Wv; value = Wsel[k*172 + n%172]
__global__ void k_prep_qkv(const float* __restrict__ Wq, const float* __restrict__ Wk,
                           const float* __restrict__ Wv) {
    int idx = blockIdx.x * blockDim.x + threadIdx.x;
    if (idx < KP_S * NP_G) {
        int k = idx / NP_G, n = idx - k * NP_G;
        float v = 0.f;
        if (k < MEMD && n < G3) {
            int sel = n / MEMD, jj = n - sel * MEMD;
            const float* W = (sel == 0) ? Wq : ((sel == 1) ? Wk : Wv);
            v = W[k * MEMD + jj];
        }
        split2(v, &g_BQh[idx], &g_BQl[idx]);
    }
}

// W1 is [344][172]: B1a[k][n] = W1[k][n], B1b[k][n] = W1[172+k][n]; shapes [192][256]
__global__ void k_prep_w1(const float* __restrict__ W1) {
    int idx = blockIdx.x * blockDim.x + threadIdx.x;
    if (idx < KP_S * NP_S) {
        int k = idx / NP_S, n = idx - k * NP_S;
        float va = 0.f, vb = 0.f;
        if (k < MEMD && n < MEMD) {
            va = W1[k * MEMD + n];
            vb = W1[(MEMD + k) * MEMD + n];
        }
        split2(va, &g_BW1ah[idx], &g_BW1al[idx]);
        split2(vb, &g_BW1bh[idx], &g_BW1bl[idx]);
    }
}

__global__ void k_prep_w2(const float* __restrict__ W2) {
    int idx = blockIdx.x * blockDim.x + threadIdx.x;
    if (idx < KP_S * NP_S) {
        int k = idx / NP_S, n = idx - k * NP_S;
        float v = (k < MEMD && n < MEMD) ? W2[k * MEMD + n] : 0.f;
        split2(v, &g_BW2h[idx], &g_BW2l[idx]);
    }
}

__global__ void k_prep_qconst(const float* __restrict__ Wq, const float* __restrict__ tb) {
    int j = threadIdx.x;
    if (j < MEMD) {
        float s = 0.f;
        for (int t = 0; t < TDD; t++)
            s += cos_acc(tb[t]) * Wq[(MEMD + t) * MEMD + j];
        g_qconst[j] = s;
    }
}

// memory -> split planes [NPAD][192], zero pads
__global__ void k_memconv(const float* __restrict__ mem, int Nn) {
    int idx = blockIdx.x * blockDim.x + threadIdx.x;
    if (idx >= NPAD * KP_S) return;
    int n = idx / KP_S, d = idx - n * KP_S;
    float v = (n < Nn && d < MEMD) ? mem[(size_t)n * MEMD + d] : 0.f;
    split2(v, &g_memh[idx], &g_meml[idx]);
}

// ---------------- build selected message matrix -> split planes [NPAD][640] ----------------
__global__ void k_build_m(const float* __restrict__ mem, const float* __restrict__ lu,
                          const float* __restrict__ ts, const float* __restrict__ ef,
                          const float* __restrict__ tw, const float* __restrict__ tb,
                          const int* __restrict__ src, const int* __restrict__ dst,
                          int Nn, int E) {
    int n = blockIdx.x;
    int tid = threadIdx.x;
    __nv_bfloat16* rh = g_Mh + (size_t)n * KP_M;
    __nv_bfloat16* rl = g_Ml + (size_t)n * KP_M;
    __shared__ int s_a, s_b, s_e, s_has;
    __shared__ float s_dt;
    if (tid == 0) {
        int p = (n < Nn) ? g_lastpos[n] : -1;
        if (p < 0) {
            s_has = 0;
        } else {
            s_has = 1;
            int e, a, b;
            if (p < E) { e = p;     a = src[e]; b = dst[e]; }
            else       { e = p - E; a = dst[e]; b = src[e]; }
            s_e = e; s_a = a; s_b = b;
            s_dt = ts[e] - lu[a];
        }
    }
    __syncthreads();
    if (!s_has) {
        __nv_bfloat16 z = __float2bfloat16(0.f);
        for (int i = tid; i < KP_M; i += blockDim.x) { rh[i] = z; rl[i] = z; }
        return;
    }
    int a = s_a, b = s_b, e = s_e;
    float dt = s_dt;
    for (int i = tid; i < KP_M; i += blockDim.x) {
        float v = 0.f;
        if (i < MEMD)                  v = mem[(size_t)a * MEMD + i];
        else if (i < 2 * MEMD)         v = mem[(size_t)b * MEMD + (i - MEMD)];
        else if (i < 2 * MEMD + FEATD) v = ef[(size_t)e * FEATD + (i - 2 * MEMD)];
        else if (i < MSGD) { int t = i - (2 * MEMD + FEATD); v = cos_acc(dt * tw[t] + tb[t]); }
        split2(v, &rh[i], &rl[i]);
    }
}

// ---------------- 3-product bf16 wmma GEMM, pre-split operands, reg double-buffer ----------
// C[M,N] (+)= A[M,Kp] @ B[Kp,Np]; bf16 hi+lo planes; fp32 C; round-1 epilogue
// (bias -> accum -> relu) with full M/N guards via staged smem tile.
// 128x128 block, BK=32, 8 warps (2x4), warp tile 64x32. Gmem loads for tile k+1
// are issued into registers before the mma burst for tile k (latency hiding).
#define GBK 32
#define APADS 40
#define BPADS 136
#define CPADS 132
#define SRAW_BYTES (128*APADS*2*2 + GBK*BPADS*2*2)   // 37888 B; Cs needs 33792 B

__global__ __launch_bounds__(256) void k_gemm3(
        const __nv_bfloat16* __restrict__ Agh, const __nv_bfloat16* __restrict__ Agl, int lda,
        const __nv_bfloat16* __restrict__ Bgh, const __nv_bfloat16* __restrict__ Bgl, int ldb,
        const float* __restrict__ bias, float* __restrict__ C,
        int M, int N, int Kp, int accum, int relu) {
    __shared__ __align__(16) unsigned char sraw[SRAW_BYTES];
    __nv_bfloat16* Ah = (__nv_bfloat16*)sraw;              // [128][APADS]
    __nv_bfloat16* Al = Ah + 128 * APADS;
    __nv_bfloat16* Bh = Al + 128 * APADS;                  // [GBK][BPADS]
    __nv_bfloat16* Bl = Bh + GBK * BPADS;
    float* Cs = (float*)sraw;

    int tid = threadIdx.x;
    int w = tid >> 5;
    int wm = w >> 2, wn = w & 3;
    int row0 = blockIdx.y * 128;
    int col0 = blockIdx.x * 128;

    wmma::fragment<wmma::accumulator, 16, 16, 16, float> acc[4][2];
#pragma unroll
    for (int i = 0; i < 4; i++)
#pragma unroll
        for (int j = 0; j < 2; j++) wmma::fill_fragment(acc[i][j], 0.f);

    // per-thread load/store coords (no bounds checks — operands fully padded)
    int ar = tid >> 1, akh = (tid & 1) * 16;   // A: 16 bf16 = 2x uint4 per plane
    int bk = tid >> 3, bns = (tid & 7) * 16;   // B: 16 bf16 = 2x uint4 per plane
    const __nv_bfloat16* pAh = Agh + (size_t)(row0 + ar) * lda + akh;
    const __nv_bfloat16* pAl = Agl + (size_t)(row0 + ar) * lda + akh;
    const __nv_bfloat16* pBh = Bgh + (size_t)bk * ldb + col0 + bns;
    const __nv_bfloat16* pBl = Bgl + (size_t)bk * ldb + col0 + bns;
    uint4* da_h = (uint4*)(Ah + ar * APADS + akh);
    uint4* da_l = (uint4*)(Al + ar * APADS + akh);
    uint4* db_h = (uint4*)(Bh + bk * BPADS + bns);
    uint4* db_l = (uint4*)(Bl + bk * BPADS + bns);

    // prefetch tile 0 into registers
    uint4 rah0, rah1, ral0, ral1, rbh0, rbh1, rbl0, rbl1;
    rah0 = ((const uint4*)pAh)[0]; rah1 = ((const uint4*)pAh)[1];
    ral0 = ((const uint4*)pAl)[0]; ral1 = ((const uint4*)pAl)[1];
    rbh0 = ((const uint4*)pBh)[0]; rbh1 = ((const uint4*)pBh)[1];
    rbl0 = ((const uint4*)pBl)[0]; rbl1 = ((const uint4*)pBl)[1];

    for (int k0 = 0; k0 < Kp; k0 += GBK) {
        __syncthreads();   // previous iteration's mma done before smem overwrite
        da_h[0] = rah0; da_h[1] = rah1;
        da_l[0] = ral0; da_l[1] = ral1;
        db_h[0] = rbh0; db_h[1] = rbh1;
        db_l[0] = rbl0; db_l[1] = rbl1;
        __syncthreads();
        // issue next tile's gmem loads now; consumed next iteration (latency hidden)
        if (k0 + GBK < Kp) {
            const uint4* qAh = (const uint4*)(pAh + k0 + GBK);
            const uint4* qAl = (const uint4*)(pAl + k0 + GBK);
            const uint4* qBh = (const uint4*)(pBh + (size_t)(k0 + GBK) * ldb);
            const uint4* qBl = (const uint4*)(pBl + (size_t)(k0 + GBK) * ldb);
            rah0 = qAh[0]; rah1 = qAh[1];
            ral0 = qAl[0]; ral1 = qAl[1];
            rbh0 = qBh[0]; rbh1 = qBh[1];
            rbl0 = qBl[0]; rbl1 = qBl[1];
        }
#pragma unroll
        for (int ks = 0; ks < GBK; ks += 16) {
            wmma::fragment<wmma::matrix_b, 16, 16, 16, __nv_bfloat16, wmma::row_major> bh[2], bl[2];
            wmma::load_matrix_sync(bh[0], Bh + ks * BPADS + wn * 32,      BPADS);
            wmma::load_matrix_sync(bh[1], Bh + ks * BPADS + wn * 32 + 16, BPADS);
            wmma::load_matrix_sync(bl[0], Bl + ks * BPADS + wn * 32,      BPADS);
            wmma::load_matrix_sync(bl[1], Bl + ks * BPADS + wn * 32 + 16, BPADS);
#pragma unroll
            for (int im = 0; im < 4; im++) {
                wmma::fragment<wmma::matrix_a, 16, 16, 16, __nv_bfloat16, wmma::row_major> ah, al;
                wmma::load_matrix_sync(ah, Ah + (wm * 64 + im * 16) * APADS + ks, APADS);
                wmma::load_matrix_sync(al, Al + (wm * 64 + im * 16) * APADS + ks, APADS);
#pragma unroll
                for (int j = 0; j < 2; j++) {
                    wmma::mma_sync(acc[im][j], ah, bh[j], acc[im][j]);
                    wmma::mma_sync(acc[im][j], ah, bl[j], acc[im][j]);
                    wmma::mma_sync(acc[im][j], al, bh[j], acc[im][j]);
                }
            }
        }
    }
    __syncthreads();   // all mma reads of smem done before Cs overlay

    // staged epilogue (round-1 semantics, full guards)
    for (int ph = 0; ph < 2; ph++) {
        if (wm == ph) {
#pragma unroll
            for (int im = 0; im < 4; im++)
#pragma unroll
                for (int j = 0; j < 2; j++)
                    wmma::store_matrix_sync(Cs + (im * 16) * CPADS + wn * 32 + j * 16,
                                            acc[im][j], CPADS, wmma::mem_row_major);
        }
        __syncthreads();
        for (int e = tid; e < 64 * 128; e += 256) {
            int rr = e >> 7, cc = e & 127;
            int gr = row0 + ph * 64 + rr, gc = col0 + cc;
            if (gr < M && gc < N) {
                float v = Cs[rr * CPADS + cc];
                if (bias) v += bias[gc];
                size_t ix = (size_t)gr * N + gc;
                if (accum) v += C[ix];
                if (relu) v = fmaxf(v, 0.f);
                C[ix] = v;
            }
        }
        __syncthreads();
    }
}

// ---------------- GRU gating + h = mem_upd + node_features -> split planes ----------------
__global__ void k_gate(const float* __restrict__ mem, const float* __restrict__ nf, int Nn) {
    int idx = blockIdx.x * blockDim.x + threadIdx.x;
    if (idx >= NPAD * KP_S) return;
    int n = idx / KP_S, d = idx - n * KP_S;
    float out = 0.f;
    if (n < Nn && d < MEMD) {
        size_t mi = (size_t)n * MEMD + d;
        float mv = mem[mi];
        float hv;
        if (g_lastpos[n] >= 0) {
            const float* gi = g_GI + (size_t)n * G3;
            const float* gh = g_GH + (size_t)n * G3;
            float r = 1.f / (1.f + expf(-(gi[d] + gh[d])));
            float z = 1.f / (1.f + expf(-(gi[MEMD + d] + gh[MEMD + d])));
            float g = tanhf(gi[2 * MEMD + d] + r * gh[2 * MEMD + d]);
            hv = (1.f - z) * g + z * mv;
        } else {
            hv = mv;
        }
        out = hv + nf[mi];
    }
    split2(out, &g_hh[idx], &g_hl[idx]);
}

// ---------------- temporal attention -> split agg planes ----------------
__global__ void k_attn(const float* __restrict__ Wk_full, const float* __restrict__ Wv_full,
                       const int* __restrict__ nbi, const float* __restrict__ nts,
                       const float* __restrict__ tw, const float* __restrict__ tb,
                       const float* __restrict__ ts, int Nn, int E) {
    int n = blockIdx.x;
    int tid = threadIdx.x;
    if (n >= Nn) {   // zero pad rows
        __nv_bfloat16 z = __float2bfloat16(0.f);
        for (int d = tid; d < KP_S; d += blockDim.x) {
            g_aggh[(size_t)n * KP_S + d] = z;
            g_aggl[(size_t)n * KP_S + d] = z;
        }
        return;
    }
    __shared__ float s_q[MEMD];
    __shared__ float s_c[2 * TDD];
    __shared__ float s_te[KNB * TDD];
    __shared__ float s_sc[2 * KNB];
    __shared__ float s_at[2 * KNB];
    __shared__ float s_wt[2 * TDD];
    __shared__ int s_nb[KNB];

    const float* Wk2 = Wk_full + MEMD * MEMD;
    const float* Wv2 = Wv_full + MEMD * MEMD;
    float t_now = __ldg(&ts[E - 1]);

    if (tid < KNB) s_nb[tid] = nbi[(size_t)n * KNB + tid];
    for (int i = tid; i < MEMD; i += blockDim.x)
        s_q[i] = g_QKV[(size_t)n * G3 + i] + g_qconst[i];
    __syncthreads();

    for (int j = tid; j < 2 * TDD; j += blockDim.x) {
        int hh = j / TDD, t = j - hh * TDD;
        const float* wr = Wk2 + (size_t)t * MEMD + hh * DHD;
        const float* qq = s_q + hh * DHD;
        float s = 0.f;
        for (int d = 0; d < DHD; d++) s += wr[d] * qq[d];
        s_c[j] = s;
    }
    for (int j = tid; j < KNB * TDD; j += blockDim.x) {
        int k = j / TDD, t = j - k * TDD;
        float dt = t_now - nts[(size_t)n * KNB + k];
        s_te[j] = cos_acc(dt * tw[t] + tb[t]);
    }
    __syncthreads();

    int wid = tid >> 5, lane = tid & 31;
    for (int p = wid; p < 2 * KNB; p += 4) {
        int k = p >> 1, hh = p & 1;
        const float* kr = g_QKV + (size_t)s_nb[k] * G3 + MEMD + hh * DHD;
        const float* qq = s_q + hh * DHD;
        float s = 0.f;
        for (int d = lane; d < DHD; d += 32) s += qq[d] * kr[d];
        const float* cc = s_c + hh * TDD;
        const float* te = s_te + k * TDD;
        for (int t = lane; t < TDD; t += 32) s += cc[t] * te[t];
        for (int o = 16; o; o >>= 1) s += __shfl_down_sync(0xffffffffu, s, o);
        if (lane == 0) s_sc[hh * KNB + k] = s * 0.10783277320343841f;  // 1/sqrt(86)
    }
    __syncthreads();

    if (tid < 2) {
        float mx = -1e30f;
        for (int k = 0; k < KNB; k++) mx = fmaxf(mx, s_sc[tid * KNB + k]);
        float sum = 0.f;
        for (int k = 0; k < KNB; k++) {
            float e = expf(s_sc[tid * KNB + k] - mx);
            s_at[tid * KNB + k] = e;
            sum += e;
        }
        float inv = 1.f / sum;
        for (int k = 0; k < KNB; k++) s_at[tid * KNB + k] *= inv;
    }
    __syncthreads();

    for (int j = tid; j < 2 * TDD; j += blockDim.x) {
        int hh = j / TDD, t = j - hh * TDD;
        float s = 0.f;
        for (int k = 0; k < KNB; k++) s += s_at[hh * KNB + k] * s_te[k * TDD + t];
        s_wt[j] = s;
    }
    __syncthreads();

    for (int d = tid; d < MEMD; d += blockDim.x) {
        int hh = d / DHD;
        float s = 0.f;
        for (int k = 0; k < KNB; k++)
            s += s_at[hh * KNB + k] * g_QKV[(size_t)s_nb[k] * G3 + 2 * MEMD + d];
        const float* wv = Wv2 + d;
        const float* wt = s_wt + hh * TDD;
        for (int t = 0; t < TDD; t++) s += wt[t] * wv[(size_t)t * MEMD];
        split2(s, &g_aggh[(size_t)n * KP_S + d], &g_aggl[(size_t)n * KP_S + d]);
    }
    // zero pad cols 172..191
    __nv_bfloat16 z = __float2bfloat16(0.f);
    for (int d = MEMD + tid; d < KP_S; d += blockDim.x) {
        g_aggh[(size_t)n * KP_S + d] = z;
        g_aggl[(size_t)n * KP_S + d] = z;
    }
}

// ---------------- T1 fp32 -> split planes ----------------
__global__ void k_t1split(int Nn) {
    int idx = blockIdx.x * blockDim.x + threadIdx.x;
    if (idx >= NPAD * KP_S) return;
    int n = idx / KP_S, d = idx - n * KP_S;
    float v = (n < Nn && d < MEMD) ? g_T1[(size_t)n * MEMD + d] : 0.f;
    split2(v, &g_t1h[idx], &g_t1l[idx]);
}

// ---------------- deterministic final reduction + classifier ----------------
__global__ void k_reduce1(int Nn) {
    int b = blockIdx.x, c = threadIdx.x;
    if (c >= MEMD) return;
    float s = 0.f;
    for (int r = 1 + b; r < Nn; r += RB) s += g_emb[(size_t)r * MEMD + c];
    g_partial[b * MEMD + c] = s;
}

__global__ void k_final(const float* __restrict__ fc2w, const float* __restrict__ fc2b,
                        float* __restrict__ out, int Nn) {
    __shared__ float tm[MEMD];
    int c = threadIdx.x;
    if (c < MEMD) {
        float s = 0.f;
        for (int b = 0; b < RB; b++) s += g_partial[b * MEMD + c];
        tm[c] = tanhf(s / (float)(Nn - 1));
    }
    __syncthreads();
    if (c == 0) {
        float l0 = fc2b[0], l1 = fc2b[1];
        for (int i = 0; i < MEMD; i++) {
            l0 += tm[i] * fc2w[i * 2 + 0];
            l1 += tm[i] * fc2w[i * 2 + 1];
        }
        float mx = fmaxf(l0, l1);
        float e0 = expf(l0 - mx), e1 = expf(l1 - mx);
        float inv = 1.f / (e0 + e1);
        out[0] = e0 * inv;
        out[1] = e1 * inv;
    }
}

// ---------------- host orchestration ----------------
extern "C" void kernel_launch(void* const* d_in, const int* in_sizes, int n_in,
                              void* d_out, int out_size) {
    const float* node_features = (const float*)d_in[0];
    const float* memory        = (const float*)d_in[1];
    const float* last_update   = (const float*)d_in[2];
    const float* timestamps    = (const float*)d_in[3];
    const float* edge_features = (const float*)d_in[4];
    const float* neighbor_ts   = (const float*)d_in[5];
    const float* time_w        = (const float*)d_in[6];
    const float* time_b        = (const float*)d_in[7];
    const float* gru_Wi        = (const float*)d_in[8];
    const float* gru_Wh        = (const float*)d_in[9];
    const float* gru_bi        = (const float*)d_in[10];
    const float* gru_bh        = (const float*)d_in[11];
    const float* Wq            = (const float*)d_in[12];
    const float* Wk            = (const float*)d_in[13];
    const float* Wv            = (const float*)d_in[14];
    const float* W1            = (const float*)d_in[15];
    const float* b1            = (const float*)d_in[16];
    const float* W2            = (const float*)d_in[17];
    const float* b2            = (const float*)d_in[18];
    const float* fc2_w         = (const float*)d_in[19];
    const float* fc2_b         = (const float*)d_in[20];
    const int*   sources       = (const int*)d_in[21];
    const int*   destinations  = (const int*)d_in[22];
    const int*   neighbor_idx  = (const int*)d_in[23];

    int N = in_sizes[0] / FEATD;
    int E = in_sizes[3];
    int MtRows = NPAD / 128;

    __nv_bfloat16 *pMh, *pMl, *pMemh, *pMeml, *pHh, *pHl, *pAh, *pAl, *pT1h, *pT1l;
    __nv_bfloat16 *pWih, *pWil, *pWhh, *pWhl, *pQh, *pQl, *pW1ah, *pW1al, *pW1bh, *pW1bl, *pW2h, *pW2l;
    float *pGI, *pGH, *pQKV, *pT1, *pEmb;
    cudaGetSymbolAddress((void**)&pMh,   g_Mh);
    cudaGetSymbolAddress((void**)&pMl,   g_Ml);
    cudaGetSymbolAddress((void**)&pMemh, g_memh);
    cudaGetSymbolAddress((void**)&pMeml, g_meml);
    cudaGetSymbolAddress((void**)&pHh,   g_hh);
    cudaGetSymbolAddress((void**)&pHl,   g_hl);
    cudaGetSymbolAddress((void**)&pAh,   g_aggh);
    cudaGetSymbolAddress((void**)&pAl,   g_aggl);
    cudaGetSymbolAddress((void**)&pT1h,  g_t1h);
    cudaGetSymbolAddress((void**)&pT1l,  g_t1l);
    cudaGetSymbolAddress((void**)&pWih,  g_BWih);
    cudaGetSymbolAddress((void**)&pWil,  g_BWil);
    cudaGetSymbolAddress((void**)&pWhh,  g_BWhh);
    cudaGetSymbolAddress((void**)&pWhl,  g_BWhl);
    cudaGetSymbolAddress((void**)&pQh,   g_BQh);
    cudaGetSymbolAddress((void**)&pQl,   g_BQl);
    cudaGetSymbolAddress((void**)&pW1ah, g_BW1ah);
    cudaGetSymbolAddress((void**)&pW1al, g_BW1al);
    cudaGetSymbolAddress((void**)&pW1bh, g_BW1bh);
    cudaGetSymbolAddress((void**)&pW1bl, g_BW1bl);
    cudaGetSymbolAddress((void**)&pW2h,  g_BW2h);
    cudaGetSymbolAddress((void**)&pW2l,  g_BW2l);
    cudaGetSymbolAddress((void**)&pGI,   g_GI);
    cudaGetSymbolAddress((void**)&pGH,   g_GH);
    cudaGetSymbolAddress((void**)&pQKV,  g_QKV);
    cudaGetSymbolAddress((void**)&pT1,   g_T1);
    cudaGetSymbolAddress((void**)&pEmb,  g_emb);

    k_init<<<(N + 255) / 256, 256>>>(N);
    k_scatter<<<(E + 255) / 256, 256>>>(sources, destinations, E);
    k_prep_wi<<<(KP_M * NP_G + 255) / 256, 256>>>(gru_Wi);
    k_build_m<<<NPAD, 128>>>(memory, last_update, timestamps, edge_features,
                             time_w, time_b, sources, destinations, N, E);
    k_memconv<<<(NPAD * KP_S + 255) / 256, 256>>>(memory, N);

    // GI = M @ WiT + bi
    k_gemm3<<<dim3(5, MtRows), 256>>>(pMh, pMl, KP_M, pWih, pWil, NP_G,
                                      gru_bi, pGI, N, G3, KP_M, 0, 0);
    k_prep_wh<<<(KP_S * NP_G + 255) / 256, 256>>>(gru_Wh);
    k_gemm3<<<dim3(5, MtRows), 256>>>(pMemh, pMeml, KP_S, pWhh, pWhl, NP_G,
                                      gru_bh, pGH, N, G3, KP_S, 0, 0);
    k_gate<<<(NPAD * KP_S + 255) / 256, 256>>>(memory, node_features, N);

    // QKV = h @ Bqkv
    k_prep_qkv<<<(KP_S * NP_G + 255) / 256, 256>>>(Wq, Wk, Wv);
    k_gemm3<<<dim3(5, MtRows), 256>>>(pHh, pHl, KP_S, pQh, pQl, NP_G,
                                      nullptr, pQKV, N, G3, KP_S, 0, 0);

    // attention
    k_prep_qconst<<<1, 192>>>(Wq, time_b);
    k_attn<<<NPAD, 128>>>(Wk, Wv, neighbor_idx, neighbor_ts, time_w, time_b,
                          timestamps, N, E);

    // MLP
    k_prep_w1<<<(KP_S * NP_S + 255) / 256, 256>>>(W1);
    k_prep_w2<<<(KP_S * NP_S + 255) / 256, 256>>>(W2);
    k_gemm3<<<dim3(2, MtRows), 256>>>(pHh, pHl, KP_S, pW1ah, pW1al, NP_S,
                                      b1, pT1, N, MEMD, KP_S, 0, 0);
    k_gemm3<<<dim3(2, MtRows), 256>>>(pAh, pAl, KP_S, pW1bh, pW1bl, NP_S,
                                      nullptr, pT1, N, MEMD, KP_S, 1, 1);
    k_t1split<<<(NPAD * KP_S + 255) / 256, 256>>>(N);
    k_gemm3<<<dim3(2, MtRows), 256>>>(pT1h, pT1l, KP_S, pW2h, pW2l, NP_S,
                                      b2, pEmb, N, MEMD, KP_S, 0, 0);

    // classifier head
    k_reduce1<<<RB, 192>>>(N);
    k_final<<<1, 192>>>(fc2_w, fc2_b, (float*)d_out, N);
}

// round 9
// speedup vs baseline: 1.3519x; 1.1333x over previous
#include <cuda_runtime.h>
#include <cuda_bf16.h>
#include <mma.h>
#include <math.h>

using namespace nvcuda;

#define MEMD 172
#define FEATD 172
#define TDD 100
#define KNB 10
#define DHD 86
#define MSGD 616          // 2*MEM + FEAT + TD
#define G3 516            // 3*MEM
#define NMAX 100000
#define NPAD 100096       // ceil(100000/128)*128 rows for A-operand buffers
#define RB 256

// padded K strides for bf16 operand buffers
#define KP_M 640          // 616 -> 640
#define KP_S 192          // 172 -> 192
// padded N strides for B operand buffers
#define NP_G 640          // 516 -> 640
#define NP_S 256          // 172 -> 256

// ---------------- device scratch ----------------
__device__ int   g_lastpos[NMAX];
// A-operand planes (single bf16 hi; explicitly zero-padded by producers)
__device__ __nv_bfloat16 g_Mh[(size_t)NPAD * KP_M];
__device__ __nv_bfloat16 g_memh[(size_t)NPAD * KP_S];
__device__ __nv_bfloat16 g_hh[(size_t)NPAD * KP_S];
__device__ __nv_bfloat16 g_aggh[(size_t)NPAD * KP_S];
__device__ __nv_bfloat16 g_t1h[(size_t)NPAD * KP_S];
// B-operand split planes [Kp][Np], explicitly zero-padded (weights: systematic -> keep hi+lo)
__device__ __nv_bfloat16 g_BWih[KP_M * NP_G];
__device__ __nv_bfloat16 g_BWil[KP_M * NP_G];
__device__ __nv_bfloat16 g_BWhh[KP_S * NP_G];
__device__ __nv_bfloat16 g_BWhl[KP_S * NP_G];
__device__ __nv_bfloat16 g_BQh[KP_S * NP_G];
__device__ __nv_bfloat16 g_BQl[KP_S * NP_G];
__device__ __nv_bfloat16 g_BW1ah[KP_S * NP_S];
__device__ __nv_bfloat16 g_BW1al[KP_S * NP_S];
__device__ __nv_bfloat16 g_BW1bh[KP_S * NP_S];
__device__ __nv_bfloat16 g_BW1bl[KP_S * NP_S];
__device__ __nv_bfloat16 g_BW2h[KP_S * NP_S];
__device__ __nv_bfloat16 g_BW2l[KP_S * NP_S];
// fp32 GEMM outputs (round-1 layouts, unpadded)
__device__ float g_GI[(size_t)NMAX * G3];
__device__ float g_GH[(size_t)NMAX * G3];
__device__ float g_QKV[(size_t)NMAX * G3];
__device__ float g_T1[(size_t)NMAX * MEMD];
__device__ float g_emb[(size_t)NMAX * MEMD];
__device__ float g_qconst[MEMD];
__device__ float g_partial[RB * MEMD];

// robust cos for large args (fast-math-safe): fp64 2*pi range reduction
__device__ __forceinline__ float cos_acc(float x) {
    double xd = (double)x;
    double q = rint(xd * 0.15915494309189535);
    float r = (float)(xd - q * 6.283185307179586);
    return cosf(r);
}

__device__ __forceinline__ void split2(float x, __nv_bfloat16* hi, __nv_bfloat16* lo) {
    __nv_bfloat16 h = __float2bfloat16(x);
    *hi = h;
    *lo = __float2bfloat16(x - __bfloat162float(h));
}

// ---------------- prep kernels ----------------
// fused: lastpos init + Wi weight split (keeps GI GEMM at launch index 3)
__global__ void k_prep_wi_init(const float* __restrict__ Wi, int N) {
    int idx = blockIdx.x * blockDim.x + threadIdx.x;
    if (idx < N) g_lastpos[idx] = -1;
    if (idx < KP_M * NP_G) {
        int k = idx / NP_G, n = idx - k * NP_G;
        float v = (k < MSGD && n < G3) ? Wi[n * MSGD + k] : 0.f;
        split2(v, &g_BWih[idx], &g_BWil[idx]);
    }
}

__global__ void k_scatter(const int* __restrict__ src, const int* __restrict__ dst, int E) {
    int e = blockIdx.x * blockDim.x + threadIdx.x;
    if (e < E) {
        atomicMax(&g_lastpos[src[e]], e);
        atomicMax(&g_lastpos[dst[e]], E + e);
    }
}

// B_Wh[k][n] = Wh[n*172+k]; shape [192][640]
__global__ void k_prep_wh(const float* __restrict__ Wh) {
    int idx = blockIdx.x * blockDim.x + threadIdx.x;
    if (idx < KP_S * NP_G) {
        int k = idx / NP_G, n = idx - k * NP_G;
        float v = (k < MEMD && n < G3) ? Wh[n * MEMD + k] : 0.f;
        split2(v, &g_BWhh[idx], &g_BWhl[idx]);
    }
}

// B_Q[k][n]: n in [0,516): sel=n/172 picks Wq/Wk/Wv; value = Wsel[k*172 + n%172]
__global__ void k_prep_qkv(const float* __restrict__ Wq, const float* __restrict__ Wk,
                           const float* __restrict__ Wv) {
    int idx = blockIdx.x * blockDim.x + threadIdx.x;
    if (idx < KP_S * NP_G) {
        int k = idx / NP_G, n = idx - k * NP_G;
        float v = 0.f;
        if (k < MEMD && n < G3) {
            int sel = n / MEMD, jj = n - sel * MEMD;
            const float* W = (sel == 0) ? Wq : ((sel == 1) ? Wk : Wv);
            v = W[k * MEMD + jj];
        }
        split2(v, &g_BQh[idx], &g_BQl[idx]);
    }
}

// W1 is [344][172]: B1a[k][n] = W1[k][n], B1b[k][n] = W1[172+k][n]; shapes [192][256]
__global__ void k_prep_w1(const float* __restrict__ W1) {
    int idx = blockIdx.x * blockDim.x + threadIdx.x;
    if (idx < KP_S * NP_S) {
        int k = idx / NP_S, n = idx - k * NP_S;
        float va = 0.f, vb = 0.f;
        if (k < MEMD && n < MEMD) {
            va = W1[k * MEMD + n];
            vb = W1[(MEMD + k) * MEMD + n];
        }
        split2(va, &g_BW1ah[idx], &g_BW1al[idx]);
        split2(vb, &g_BW1bh[idx], &g_BW1bl[idx]);
    }
}

__global__ void k_prep_w2(const float* __restrict__ W2) {
    int idx = blockIdx.x * blockDim.x + threadIdx.x;
    if (idx < KP_S * NP_S) {
        int k = idx / NP_S, n = idx - k * NP_S;
        float v = (k < MEMD && n < MEMD) ? W2[k * MEMD + n] : 0.f;
        split2(v, &g_BW2h[idx], &g_BW2l[idx]);
    }
}

__global__ void k_prep_qconst(const float* __restrict__ Wq, const float* __restrict__ tb) {
    int j = threadIdx.x;
    if (j < MEMD) {
        float s = 0.f;
        for (int t = 0; t < TDD; t++)
            s += cos_acc(tb[t]) * Wq[(MEMD + t) * MEMD + j];
        g_qconst[j] = s;
    }
}

// memory -> bf16 plane [NPAD][192], zero pads
__global__ void k_memconv(const float* __restrict__ mem, int Nn) {
    int idx = blockIdx.x * blockDim.x + threadIdx.x;
    if (idx >= NPAD * KP_S) return;
    int n = idx / KP_S, d = idx - n * KP_S;
    float v = (n < Nn && d < MEMD) ? mem[(size_t)n * MEMD + d] : 0.f;
    g_memh[idx] = __float2bfloat16(v);
}

// ---------------- build selected message matrix -> bf16 plane [NPAD][640] ----------------
__global__ void k_build_m(const float* __restrict__ mem, const float* __restrict__ lu,
                          const float* __restrict__ ts, const float* __restrict__ ef,
                          const float* __restrict__ tw, const float* __restrict__ tb,
                          const int* __restrict__ src, const int* __restrict__ dst,
                          int Nn, int E) {
    int n = blockIdx.x;
    int tid = threadIdx.x;
    __nv_bfloat16* rh = g_Mh + (size_t)n * KP_M;
    __shared__ int s_a, s_b, s_e, s_has;
    __shared__ float s_dt;
    if (tid == 0) {
        int p = (n < Nn) ? g_lastpos[n] : -1;
        if (p < 0) {
            s_has = 0;
        } else {
            s_has = 1;
            int e, a, b;
            if (p < E) { e = p;     a = src[e]; b = dst[e]; }
            else       { e = p - E; a = dst[e]; b = src[e]; }
            s_e = e; s_a = a; s_b = b;
            s_dt = ts[e] - lu[a];
        }
    }
    __syncthreads();
    if (!s_has) {
        __nv_bfloat16 z = __float2bfloat16(0.f);
        for (int i = tid; i < KP_M; i += blockDim.x) rh[i] = z;
        return;
    }
    int a = s_a, b = s_b, e = s_e;
    float dt = s_dt;
    for (int i = tid; i < KP_M; i += blockDim.x) {
        float v = 0.f;
        if (i < MEMD)                  v = mem[(size_t)a * MEMD + i];
        else if (i < 2 * MEMD)         v = mem[(size_t)b * MEMD + (i - MEMD)];
        else if (i < 2 * MEMD + FEATD) v = ef[(size_t)e * FEATD + (i - 2 * MEMD)];
        else if (i < MSGD) { int t = i - (2 * MEMD + FEATD); v = cos_acc(dt * tw[t] + tb[t]); }
        rh[i] = __float2bfloat16(v);
    }
}

// ---------------- 2-product bf16 wmma GEMM: C (+)= Ah @ (Bh + Bl) ------------------------
// A single bf16 plane (activation: random rounding, averages out); B hi+lo (weights:
// systematic error must be corrected). fp32 C, round-1 epilogue (bias -> accum -> relu)
// with full M/N guards via staged smem tile. 128x128 block, BK=32, 8 warps (2x4),
// warp tile 64x32. Reg prefetch of tile k+1 hides gmem latency.
#define GBK 32
#define APADS 40
#define BPADS 136
#define CPADS 132
#define SRAW_BYTES (64 * CPADS * 4)   // 33792; A(10240)+Bh(8704)+Bl(8704)=27648 fits

__global__ __launch_bounds__(256) void k_gemm2(
        const __nv_bfloat16* __restrict__ Agh, int lda,
        const __nv_bfloat16* __restrict__ Bgh, const __nv_bfloat16* __restrict__ Bgl, int ldb,
        const float* __restrict__ bias, float* __restrict__ C,
        int M, int N, int Kp, int accum, int relu) {
    __shared__ __align__(16) unsigned char sraw[SRAW_BYTES];
    __nv_bfloat16* Ah = (__nv_bfloat16*)sraw;              // [128][APADS]
    __nv_bfloat16* Bh = Ah + 128 * APADS;                  // [GBK][BPADS]
    __nv_bfloat16* Bl = Bh + GBK * BPADS;
    float* Cs = (float*)sraw;

    int tid = threadIdx.x;
    int w = tid >> 5;
    int wm = w >> 2, wn = w & 3;
    int row0 = blockIdx.y * 128;
    int col0 = blockIdx.x * 128;

    wmma::fragment<wmma::accumulator, 16, 16, 16, float> acc[4][2];
#pragma unroll
    for (int i = 0; i < 4; i++)
#pragma unroll
        for (int j = 0; j < 2; j++) wmma::fill_fragment(acc[i][j], 0.f);

    // per-thread load/store coords (no bounds checks — operands fully padded)
    int ar = tid >> 1, akh = (tid & 1) * 16;   // A: 16 bf16 = 2x uint4
    int bk = tid >> 3, bns = (tid & 7) * 16;   // B: 16 bf16 = 2x uint4 per plane
    const __nv_bfloat16* pAh = Agh + (size_t)(row0 + ar) * lda + akh;
    const __nv_bfloat16* pBh = Bgh + (size_t)bk * ldb + col0 + bns;
    const __nv_bfloat16* pBl = Bgl + (size_t)bk * ldb + col0 + bns;
    uint4* da_h = (uint4*)(Ah + ar * APADS + akh);
    uint4* db_h = (uint4*)(Bh + bk * BPADS + bns);
    uint4* db_l = (uint4*)(Bl + bk * BPADS + bns);

    // prefetch tile 0 into registers
    uint4 rah0, rah1, rbh0, rbh1, rbl0, rbl1;
    rah0 = ((const uint4*)pAh)[0]; rah1 = ((const uint4*)pAh)[1];
    rbh0 = ((const uint4*)pBh)[0]; rbh1 = ((const uint4*)pBh)[1];
    rbl0 = ((const uint4*)pBl)[0]; rbl1 = ((const uint4*)pBl)[1];

    for (int k0 = 0; k0 < Kp; k0 += GBK) {
        __syncthreads();   // previous iteration's mma done before smem overwrite
        da_h[0] = rah0; da_h[1] = rah1;
        db_h[0] = rbh0; db_h[1] = rbh1;
        db_l[0] = rbl0; db_l[1] = rbl1;
        __syncthreads();
        if (k0 + GBK < Kp) {
            const uint4* qAh = (const uint4*)(pAh + k0 + GBK);
            const uint4* qBh = (const uint4*)(pBh + (size_t)(k0 + GBK) * ldb);
            const uint4* qBl = (const uint4*)(pBl + (size_t)(k0 + GBK) * ldb);
            rah0 = qAh[0]; rah1 = qAh[1];
            rbh0 = qBh[0]; rbh1 = qBh[1];
            rbl0 = qBl[0]; rbl1 = qBl[1];
        }
#pragma unroll
        for (int ks = 0; ks < GBK; ks += 16) {
            wmma::fragment<wmma::matrix_b, 16, 16, 16, __nv_bfloat16, wmma::row_major> bh[2], bl[2];
            wmma::load_matrix_sync(bh[0], Bh + ks * BPADS + wn * 32,      BPADS);
            wmma::load_matrix_sync(bh[1], Bh + ks * BPADS + wn * 32 + 16, BPADS);
            wmma::load_matrix_sync(bl[0], Bl + ks * BPADS + wn * 32,      BPADS);
            wmma::load_matrix_sync(bl[1], Bl + ks * BPADS + wn * 32 + 16, BPADS);
#pragma unroll
            for (int im = 0; im < 4; im++) {
                wmma::fragment<wmma::matrix_a, 16, 16, 16, __nv_bfloat16, wmma::row_major> ah;
                wmma::load_matrix_sync(ah, Ah + (wm * 64 + im * 16) * APADS + ks, APADS);
#pragma unroll
                for (int j = 0; j < 2; j++) {
                    wmma::mma_sync(acc[im][j], ah, bh[j], acc[im][j]);
                    wmma::mma_sync(acc[im][j], ah, bl[j], acc[im][j]);
                }
            }
        }
    }
    __syncthreads();   // all mma reads of smem done before Cs overlay

    // staged epilogue (round-1 semantics, full guards)
    for (int ph = 0; ph < 2; ph++) {
        if (wm == ph) {
#pragma unroll
            for (int im = 0; im < 4; im++)
#pragma unroll
                for (int j = 0; j < 2; j++)
                    wmma::store_matrix_sync(Cs + (im * 16) * CPADS + wn * 32 + j * 16,
                                            acc[im][j], CPADS, wmma::mem_row_major);
        }
        __syncthreads();
        for (int e = tid; e < 64 * 128; e += 256) {
            int rr = e >> 7, cc = e & 127;
            int gr = row0 + ph * 64 + rr, gc = col0 + cc;
            if (gr < M && gc < N) {
                float v = Cs[rr * CPADS + cc];
                if (bias) v += bias[gc];
                size_t ix = (size_t)gr * N + gc;
                if (accum) v += C[ix];
                if (relu) v = fmaxf(v, 0.f);
                C[ix] = v;
            }
        }
        __syncthreads();
    }
}

// ---------------- GRU gating + h = mem_upd + node_features -> bf16 plane ----------------
__global__ void k_gate(const float* __restrict__ mem, const float* __restrict__ nf, int Nn) {
    int idx = blockIdx.x * blockDim.x + threadIdx.x;
    if (idx >= NPAD * KP_S) return;
    int n = idx / KP_S, d = idx - n * KP_S;
    float out = 0.f;
    if (n < Nn && d < MEMD) {
        size_t mi = (size_t)n * MEMD + d;
        float mv = mem[mi];
        float hv;
        if (g_lastpos[n] >= 0) {
            const float* gi = g_GI + (size_t)n * G3;
            const float* gh = g_GH + (size_t)n * G3;
            float r = 1.f / (1.f + expf(-(gi[d] + gh[d])));
            float z = 1.f / (1.f + expf(-(gi[MEMD + d] + gh[MEMD + d])));
            float g = tanhf(gi[2 * MEMD + d] + r * gh[2 * MEMD + d]);
            hv = (1.f - z) * g + z * mv;
        } else {
            hv = mv;
        }
        out = hv + nf[mi];
    }
    g_hh[idx] = __float2bfloat16(out);
}

// ---------------- temporal attention -> bf16 agg plane ----------------
__global__ void k_attn(const float* __restrict__ Wk_full, const float* __restrict__ Wv_full,
                       const int* __restrict__ nbi, const float* __restrict__ nts,
                       const float* __restrict__ tw, const float* __restrict__ tb,
                       const float* __restrict__ ts, int Nn, int E) {
    int n = blockIdx.x;
    int tid = threadIdx.x;
    if (n >= Nn) {
        __nv_bfloat16 z = __float2bfloat16(0.f);
        for (int d = tid; d < KP_S; d += blockDim.x)
            g_aggh[(size_t)n * KP_S + d] = z;
        return;
    }
    __shared__ float s_q[MEMD];
    __shared__ float s_c[2 * TDD];
    __shared__ float s_te[KNB * TDD];
    __shared__ float s_sc[2 * KNB];
    __shared__ float s_at[2 * KNB];
    __shared__ float s_wt[2 * TDD];
    __shared__ int s_nb[KNB];

    const float* Wk2 = Wk_full + MEMD * MEMD;
    const float* Wv2 = Wv_full + MEMD * MEMD;
    float t_now = __ldg(&ts[E - 1]);

    if (tid < KNB) s_nb[tid] = nbi[(size_t)n * KNB + tid];
    for (int i = tid; i < MEMD; i += blockDim.x)
        s_q[i] = g_QKV[(size_t)n * G3 + i] + g_qconst[i];
    __syncthreads();

    for (int j = tid; j < 2 * TDD; j += blockDim.x) {
        int hh = j / TDD, t = j - hh * TDD;
        const float* wr = Wk2 + (size_t)t * MEMD + hh * DHD;
        const float* qq = s_q + hh * DHD;
        float s = 0.f;
        for (int d = 0; d < DHD; d++) s += wr[d] * qq[d];
        s_c[j] = s;
    }
    for (int j = tid; j < KNB * TDD; j += blockDim.x) {
        int k = j / TDD, t = j - k * TDD;
        float dt = t_now - nts[(size_t)n * KNB + k];
        s_te[j] = cos_acc(dt * tw[t] + tb[t]);
    }
    __syncthreads();

    int wid = tid >> 5, lane = tid & 31;
    for (int p = wid; p < 2 * KNB; p += 4) {
        int k = p >> 1, hh = p & 1;
        const float* kr = g_QKV + (size_t)s_nb[k] * G3 + MEMD + hh * DHD;
        const float* qq = s_q + hh * DHD;
        float s = 0.f;
        for (int d = lane; d < DHD; d += 32) s += qq[d] * kr[d];
        const float* cc = s_c + hh * TDD;
        const float* te = s_te + k * TDD;
        for (int t = lane; t < TDD; t += 32) s += cc[t] * te[t];
        for (int o = 16; o; o >>= 1) s += __shfl_down_sync(0xffffffffu, s, o);
        if (lane == 0) s_sc[hh * KNB + k] = s * 0.10783277320343841f;  // 1/sqrt(86)
    }
    __syncthreads();

    if (tid < 2) {
        float mx = -1e30f;
        for (int k = 0; k < KNB; k++) mx = fmaxf(mx, s_sc[tid * KNB + k]);
        float sum = 0.f;
        for (int k = 0; k < KNB; k++) {
            float e = expf(s_sc[tid * KNB + k] - mx);
            s_at[tid * KNB + k] = e;
            sum += e;
        }
        float inv = 1.f / sum;
        for (int k = 0; k < KNB; k++) s_at[tid * KNB + k] *= inv;
    }
    __syncthreads();

    for (int j = tid; j < 2 * TDD; j += blockDim.x) {
        int hh = j / TDD, t = j - hh * TDD;
        float s = 0.f;
        for (int k = 0; k < KNB; k++) s += s_at[hh * KNB + k] * s_te[k * TDD + t];
        s_wt[j] = s;
    }
    __syncthreads();

    for (int d = tid; d < MEMD; d += blockDim.x) {
        int hh = d / DHD;
        float s = 0.f;
        for (int k = 0; k < KNB; k++)
            s += s_at[hh * KNB + k] * g_QKV[(size_t)s_nb[k] * G3 + 2 * MEMD + d];
        const float* wv = Wv2 + d;
        const float* wt = s_wt + hh * TDD;
        for (int t = 0; t < TDD; t++) s += wt[t] * wv[(size_t)t * MEMD];
        g_aggh[(size_t)n * KP_S + d] = __float2bfloat16(s);
    }
    __nv_bfloat16 z = __float2bfloat16(0.f);
    for (int d = MEMD + tid; d < KP_S; d += blockDim.x)
        g_aggh[(size_t)n * KP_S + d] = z;
}

// ---------------- T1 fp32 -> bf16 plane ----------------
__global__ void k_t1split(int Nn) {
    int idx = blockIdx.x * blockDim.x + threadIdx.x;
    if (idx >= NPAD * KP_S) return;
    int n = idx / KP_S, d = idx - n * KP_S;
    float v = (n < Nn && d < MEMD) ? g_T1[(size_t)n * MEMD + d] : 0.f;
    g_t1h[idx] = __float2bfloat16(v);
}

// ---------------- deterministic final reduction + classifier ----------------
__global__ void k_reduce1(int Nn) {
    int b = blockIdx.x, c = threadIdx.x;
    if (c >= MEMD) return;
    float s = 0.f;
    for (int r = 1 + b; r < Nn; r += RB) s += g_emb[(size_t)r * MEMD + c];
    g_partial[b * MEMD + c] = s;
}

__global__ void k_final(const float* __restrict__ fc2w, const float* __restrict__ fc2b,
                        float* __restrict__ out, int Nn) {
    __shared__ float tm[MEMD];
    int c = threadIdx.x;
    if (c < MEMD) {
        float s = 0.f;
        for (int b = 0; b < RB; b++) s += g_partial[b * MEMD + c];
        tm[c] = tanhf(s / (float)(Nn - 1));
    }
    __syncthreads();
    if (c == 0) {
        float l0 = fc2b[0], l1 = fc2b[1];
        for (int i = 0; i < MEMD; i++) {
            l0 += tm[i] * fc2w[i * 2 + 0];
            l1 += tm[i] * fc2w[i * 2 + 1];
        }
        float mx = fmaxf(l0, l1);
        float e0 = expf(l0 - mx), e1 = expf(l1 - mx);
        float inv = 1.f / (e0 + e1);
        out[0] = e0 * inv;
        out[1] = e1 * inv;
    }
}

// ---------------- host orchestration ----------------
extern "C" void kernel_launch(void* const* d_in, const int* in_sizes, int n_in,
                              void* d_out, int out_size) {
    const float* node_features = (const float*)d_in[0];
    const float* memory        = (const float*)d_in[1];
    const float* last_update   = (const float*)d_in[2];
    const float* timestamps    = (const float*)d_in[3];
    const float* edge_features = (const float*)d_in[4];
    const float* neighbor_ts   = (const float*)d_in[5];
    const float* time_w        = (const float*)d_in[6];
    const float* time_b        = (const float*)d_in[7];
    const float* gru_Wi        = (const float*)d_in[8];
    const float* gru_Wh        = (const float*)d_in[9];
    const float* gru_bi        = (const float*)d_in[10];
    const float* gru_bh        = (const float*)d_in[11];
    const float* Wq            = (const float*)d_in[12];
    const float* Wk            = (const float*)d_in[13];
    const float* Wv            = (const float*)d_in[14];
    const float* W1            = (const float*)d_in[15];
    const float* b1            = (const float*)d_in[16];
    const float* W2            = (const float*)d_in[17];
    const float* b2            = (const float*)d_in[18];
    const float* fc2_w         = (const float*)d_in[19];
    const float* fc2_b         = (const float*)d_in[20];
    const int*   sources       = (const int*)d_in[21];
    const int*   destinations  = (const int*)d_in[22];
    const int*   neighbor_idx  = (const int*)d_in[23];

    int N = in_sizes[0] / FEATD;
    int E = in_sizes[3];
    int MtRows = NPAD / 128;

    __nv_bfloat16 *pMh, *pMemh, *pHh, *pAh, *pT1h;
    __nv_bfloat16 *pWih, *pWil, *pWhh, *pWhl, *pQh, *pQl, *pW1ah, *pW1al, *pW1bh, *pW1bl, *pW2h, *pW2l;
    float *pGI, *pGH, *pQKV, *pT1, *pEmb;
    cudaGetSymbolAddress((void**)&pMh,   g_Mh);
    cudaGetSymbolAddress((void**)&pMemh, g_memh);
    cudaGetSymbolAddress((void**)&pHh,   g_hh);
    cudaGetSymbolAddress((void**)&pAh,   g_aggh);
    cudaGetSymbolAddress((void**)&pT1h,  g_t1h);
    cudaGetSymbolAddress((void**)&pWih,  g_BWih);
    cudaGetSymbolAddress((void**)&pWil,  g_BWil);
    cudaGetSymbolAddress((void**)&pWhh,  g_BWhh);
    cudaGetSymbolAddress((void**)&pWhl,  g_BWhl);
    cudaGetSymbolAddress((void**)&pQh,   g_BQh);
    cudaGetSymbolAddress((void**)&pQl,   g_BQl);
    cudaGetSymbolAddress((void**)&pW1ah, g_BW1ah);
    cudaGetSymbolAddress((void**)&pW1al, g_BW1al);
    cudaGetSymbolAddress((void**)&pW1bh, g_BW1bh);
    cudaGetSymbolAddress((void**)&pW1bl, g_BW1bl);
    cudaGetSymbolAddress((void**)&pW2h,  g_BW2h);
    cudaGetSymbolAddress((void**)&pW2l,  g_BW2l);
    cudaGetSymbolAddress((void**)&pGI,   g_GI);
    cudaGetSymbolAddress((void**)&pGH,   g_GH);
    cudaGetSymbolAddress((void**)&pQKV,  g_QKV);
    cudaGetSymbolAddress((void**)&pT1,   g_T1);
    cudaGetSymbolAddress((void**)&pEmb,  g_emb);

    // launch order: GI GEMM at my-index 3 (harness adds ~2 internal launches; ncu -s 5)
    k_prep_wi_init<<<(KP_M * NP_G + 255) / 256, 256>>>(gru_Wi, N);          // 0
    k_scatter<<<(E + 255) / 256, 256>>>(sources, destinations, E);          // 1
    k_build_m<<<NPAD, 128>>>(memory, last_update, timestamps, edge_features,
                             time_w, time_b, sources, destinations, N, E);  // 2
    k_gemm2<<<dim3(5, MtRows), 256>>>(pMh, KP_M, pWih, pWil, NP_G,
                                      gru_bi, pGI, N, G3, KP_M, 0, 0);      // 3 (profiled)
    k_memconv<<<(NPAD * KP_S + 255) / 256, 256>>>(memory, N);               // 4
    k_prep_wh<<<(KP_S * NP_G + 255) / 256, 256>>>(gru_Wh);                  // 5
    k_gemm2<<<dim3(5, MtRows), 256>>>(pMemh, KP_S, pWhh, pWhl, NP_G,
                                      gru_bh, pGH, N, G3, KP_S, 0, 0);      // 6
    k_gate<<<(NPAD * KP_S + 255) / 256, 256>>>(memory, node_features, N);   // 7

    // QKV = h @ Bqkv
    k_prep_qkv<<<(KP_S * NP_G + 255) / 256, 256>>>(Wq, Wk, Wv);
    k_gemm2<<<dim3(5, MtRows), 256>>>(pHh, KP_S, pQh, pQl, NP_G,
                                      nullptr, pQKV, N, G3, KP_S, 0, 0);

    // attention
    k_prep_qconst<<<1, 192>>>(Wq, time_b);
    k_attn<<<NPAD, 128>>>(Wk, Wv, neighbor_idx, neighbor_ts, time_w, time_b,
                          timestamps, N, E);

    // MLP
    k_prep_w1<<<(KP_S * NP_S + 255) / 256, 256>>>(W1);
    k_prep_w2<<<(KP_S * NP_S + 255) / 256, 256>>>(W2);
    k_gemm2<<<dim3(2, MtRows), 256>>>(pHh, KP_S, pW1ah, pW1al, NP_S,
                                      b1, pT1, N, MEMD, KP_S, 0, 0);
    k_gemm2<<<dim3(2, MtRows), 256>>>(pAh, KP_S, pW1bh, pW1bl, NP_S,
                                      nullptr, pT1, N, MEMD, KP_S, 1, 1);
    k_t1split<<<(NPAD * KP_S + 255) / 256, 256>>>(N);
    k_gemm2<<<dim3(2, MtRows), 256>>>(pT1h, KP_S, pW2h, pW2l, NP_S,
                                      b2, pEmb, N, MEMD, KP_S, 0, 0);

    // classifier head
    k_reduce1<<<RB, 192>>>(N);
    k_final<<<1, 192>>>(fc2_w, fc2_b, (float*)d_out, N);
}

// round 10
// speedup vs baseline: 1.3695x; 1.0130x over previous
#include <cuda_runtime.h>
#include <cuda_bf16.h>
#include <mma.h>
#include <math.h>

using namespace nvcuda;

#define MEMD 172
#define FEATD 172
#define TDD 100
#define KNB 10
#define DHD 86
#define MSGD 616          // 2*MEM + FEAT + TD
#define G3 516            // 3*MEM
#define NMAX 100000
#define NPAD 100096       // ceil(100000/128)*128 rows for A-operand buffers
#define RB 256

// padded K strides for bf16 operand buffers
#define KP_M 640          // 616 -> 640
#define KP_S 192          // 172 -> 192
// padded N strides for B operand buffers
#define NP_G 640          // 516 -> 640
#define NP_S 256          // 172 -> 256

// ---------------- device scratch ----------------
__device__ int   g_lastpos[NMAX];
// A-operand planes (single bf16 hi; explicitly zero-padded by producers)
__device__ __nv_bfloat16 g_Mh[(size_t)NPAD * KP_M];
__device__ __nv_bfloat16 g_memh[(size_t)NPAD * KP_S];
__device__ __nv_bfloat16 g_hh[(size_t)NPAD * KP_S];
__device__ __nv_bfloat16 g_aggh[(size_t)NPAD * KP_S];
__device__ __nv_bfloat16 g_t1h[(size_t)NPAD * KP_S];
// B-operand split planes [Kp][Np], explicitly zero-padded (weights: systematic -> keep hi+lo)
__device__ __nv_bfloat16 g_BWih[KP_M * NP_G];
__device__ __nv_bfloat16 g_BWil[KP_M * NP_G];
__device__ __nv_bfloat16 g_BWhh[KP_S * NP_G];
__device__ __nv_bfloat16 g_BWhl[KP_S * NP_G];
__device__ __nv_bfloat16 g_BQh[KP_S * NP_G];
__device__ __nv_bfloat16 g_BQl[KP_S * NP_G];
__device__ __nv_bfloat16 g_BW1ah[KP_S * NP_S];
__device__ __nv_bfloat16 g_BW1al[KP_S * NP_S];
__device__ __nv_bfloat16 g_BW1bh[KP_S * NP_S];
__device__ __nv_bfloat16 g_BW1bl[KP_S * NP_S];
__device__ __nv_bfloat16 g_BW2h[KP_S * NP_S];
__device__ __nv_bfloat16 g_BW2l[KP_S * NP_S];
// fp32 GEMM outputs (round-1 layouts, unpadded)
__device__ float g_GI[(size_t)NMAX * G3];
__device__ float g_GH[(size_t)NMAX * G3];
__device__ float g_QKV[(size_t)NMAX * G3];
__device__ float g_T1[(size_t)NMAX * MEMD];
__device__ float g_emb[(size_t)NMAX * MEMD];
__device__ float g_qconst[MEMD];
__device__ float g_partial[RB * MEMD];

// robust cos for large args (fast-math-safe): fp64 2*pi range reduction
__device__ __forceinline__ float cos_acc(float x) {
    double xd = (double)x;
    double q = rint(xd * 0.15915494309189535);
    float r = (float)(xd - q * 6.283185307179586);
    return cosf(r);
}

__device__ __forceinline__ void split2(float x, __nv_bfloat16* hi, __nv_bfloat16* lo) {
    __nv_bfloat16 h = __float2bfloat16(x);
    *hi = h;
    *lo = __float2bfloat16(x - __bfloat162float(h));
}

// ---------------- prep kernels ----------------
// fused: lastpos init + Wi weight split (keeps GI GEMM at launch index 3)
__global__ void k_prep_wi_init(const float* __restrict__ Wi, int N) {
    int idx = blockIdx.x * blockDim.x + threadIdx.x;
    if (idx < N) g_lastpos[idx] = -1;
    if (idx < KP_M * NP_G) {
        int k = idx / NP_G, n = idx - k * NP_G;
        float v = (k < MSGD && n < G3) ? Wi[n * MSGD + k] : 0.f;
        split2(v, &g_BWih[idx], &g_BWil[idx]);
    }
}

__global__ void k_scatter(const int* __restrict__ src, const int* __restrict__ dst, int E) {
    int e = blockIdx.x * blockDim.x + threadIdx.x;
    if (e < E) {
        atomicMax(&g_lastpos[src[e]], e);
        atomicMax(&g_lastpos[dst[e]], E + e);
    }
}

// B_Wh[k][n] = Wh[n*172+k]; shape [192][640]
__global__ void k_prep_wh(const float* __restrict__ Wh) {
    int idx = blockIdx.x * blockDim.x + threadIdx.x;
    if (idx < KP_S * NP_G) {
        int k = idx / NP_G, n = idx - k * NP_G;
        float v = (k < MEMD && n < G3) ? Wh[n * MEMD + k] : 0.f;
        split2(v, &g_BWhh[idx], &g_BWhl[idx]);
    }
}

// B_Q[k][n]: n in [0,516): sel=n/172 picks Wq/Wk/Wv; value = Wsel[k*172 + n%172]
__global__ void k_prep_qkv(const float* __restrict__ Wq, const float* __restrict__ Wk,
                           const float* __restrict__ Wv) {
    int idx = blockIdx.x * blockDim.x + threadIdx.x;
    if (idx < KP_S * NP_G) {
        int k = idx / NP_G, n = idx - k * NP_G;
        float v = 0.f;
        if (k < MEMD && n < G3) {
            int sel = n / MEMD, jj = n - sel * MEMD;
            const float* W = (sel == 0) ? Wq : ((sel == 1) ? Wk : Wv);
            v = W[k * MEMD + jj];
        }
        split2(v, &g_BQh[idx], &g_BQl[idx]);
    }
}

// W1 is [344][172]: B1a[k][n] = W1[k][n], B1b[k][n] = W1[172+k][n]; shapes [192][256]
__global__ void k_prep_w1(const float* __restrict__ W1) {
    int idx = blockIdx.x * blockDim.x + threadIdx.x;
    if (idx < KP_S * NP_S) {
        int k = idx / NP_S, n = idx - k * NP_S;
        float va = 0.f, vb = 0.f;
        if (k < MEMD && n < MEMD) {
            va = W1[k * MEMD + n];
            vb = W1[(MEMD + k) * MEMD + n];
        }
        split2(va, &g_BW1ah[idx], &g_BW1al[idx]);
        split2(vb, &g_BW1bh[idx], &g_BW1bl[idx]);
    }
}

__global__ void k_prep_w2(const float* __restrict__ W2) {
    int idx = blockIdx.x * blockDim.x + threadIdx.x;
    if (idx < KP_S * NP_S) {
        int k = idx / NP_S, n = idx - k * NP_S;
        float v = (k < MEMD && n < MEMD) ? W2[k * MEMD + n] : 0.f;
        split2(v, &g_BW2h[idx], &g_BW2l[idx]);
    }
}

__global__ void k_prep_qconst(const float* __restrict__ Wq, const float* __restrict__ tb) {
    int j = threadIdx.x;
    if (j < MEMD) {
        float s = 0.f;
        for (int t = 0; t < TDD; t++)
            s += cos_acc(tb[t]) * Wq[(MEMD + t) * MEMD + j];
        g_qconst[j] = s;
    }
}

// memory -> bf16 plane [NPAD][192], zero pads
__global__ void k_memconv(const float* __restrict__ mem, int Nn) {
    int idx = blockIdx.x * blockDim.x + threadIdx.x;
    if (idx >= NPAD * KP_S) return;
    int n = idx / KP_S, d = idx - n * KP_S;
    float v = (n < Nn && d < MEMD) ? mem[(size_t)n * MEMD + d] : 0.f;
    g_memh[idx] = __float2bfloat16(v);
}

// ---------------- build selected message matrix -> bf16 plane [NPAD][640] ----------------
__global__ void k_build_m(const float* __restrict__ mem, const float* __restrict__ lu,
                          const float* __restrict__ ts, const float* __restrict__ ef,
                          const float* __restrict__ tw, const float* __restrict__ tb,
                          const int* __restrict__ src, const int* __restrict__ dst,
                          int Nn, int E) {
    int n = blockIdx.x;
    int tid = threadIdx.x;
    __nv_bfloat16* rh = g_Mh + (size_t)n * KP_M;
    __shared__ int s_a, s_b, s_e, s_has;
    __shared__ float s_dt;
    if (tid == 0) {
        int p = (n < Nn) ? g_lastpos[n] : -1;
        if (p < 0) {
            s_has = 0;
        } else {
            s_has = 1;
            int e, a, b;
            if (p < E) { e = p;     a = src[e]; b = dst[e]; }
            else       { e = p - E; a = dst[e]; b = src[e]; }
            s_e = e; s_a = a; s_b = b;
            s_dt = ts[e] - lu[a];
        }
    }
    __syncthreads();
    if (!s_has) {
        __nv_bfloat16 z = __float2bfloat16(0.f);
        for (int i = tid; i < KP_M; i += blockDim.x) rh[i] = z;
        return;
    }
    int a = s_a, b = s_b, e = s_e;
    float dt = s_dt;
    for (int i = tid; i < KP_M; i += blockDim.x) {
        float v = 0.f;
        if (i < MEMD)                  v = mem[(size_t)a * MEMD + i];
        else if (i < 2 * MEMD)         v = mem[(size_t)b * MEMD + (i - MEMD)];
        else if (i < 2 * MEMD + FEATD) v = ef[(size_t)e * FEATD + (i - 2 * MEMD)];
        else if (i < MSGD) { int t = i - (2 * MEMD + FEATD); v = cos_acc(dt * tw[t] + tb[t]); }
        rh[i] = __float2bfloat16(v);
    }
}

// ---------------- 2-product bf16 wmma GEMM: C (+)= Ah @ (Bh + Bl) ------------------------
// Double-buffered dynamic smem, 1 sync/iter; __launch_bounds__(256,2) for 2 CTAs/SM.
// 128x128 block, BK=32, 8 warps (2x4), warp tile 64x32. fp32 C, round-1 epilogue
// (bias -> accum -> relu) with full M/N guards via staged smem tile overlay.
#define GBK 32
#define APADS 40
#define BPADS 136
#define CPADS 132
// dynamic smem byte offsets
#define SM_A0   0
#define SM_A1   10240
#define SM_BH0  20480
#define SM_BL0  29184
#define SM_BH1  37888
#define SM_BL1  46592
#define SM_TOT  55296        // Cs overlay needs 64*132*4 = 33792 <= SM_TOT

__global__ __launch_bounds__(256, 2) void k_gemm2(
        const __nv_bfloat16* __restrict__ Agh, int lda,
        const __nv_bfloat16* __restrict__ Bgh, const __nv_bfloat16* __restrict__ Bgl, int ldb,
        const float* __restrict__ bias, float* __restrict__ C,
        int M, int N, int Kp, int accum, int relu) {
    extern __shared__ __align__(16) unsigned char sraw[];
    __nv_bfloat16* Abuf[2] = { (__nv_bfloat16*)(sraw + SM_A0),  (__nv_bfloat16*)(sraw + SM_A1)  };
    __nv_bfloat16* Bhb[2]  = { (__nv_bfloat16*)(sraw + SM_BH0), (__nv_bfloat16*)(sraw + SM_BH1) };
    __nv_bfloat16* Blb[2]  = { (__nv_bfloat16*)(sraw + SM_BL0), (__nv_bfloat16*)(sraw + SM_BL1) };
    float* Cs = (float*)sraw;

    int tid = threadIdx.x;
    int w = tid >> 5;
    int wm = w >> 2, wn = w & 3;
    int row0 = blockIdx.y * 128;
    int col0 = blockIdx.x * 128;

    wmma::fragment<wmma::accumulator, 16, 16, 16, float> acc[4][2];
#pragma unroll
    for (int i = 0; i < 4; i++)
#pragma unroll
        for (int j = 0; j < 2; j++) wmma::fill_fragment(acc[i][j], 0.f);

    // per-thread load/store coords (no bounds checks — operands fully padded)
    int ar = tid >> 1, akh = (tid & 1) * 16;   // A: 16 bf16 = 2x uint4
    int bk = tid >> 3, bns = (tid & 7) * 16;   // B: 16 bf16 = 2x uint4 per plane
    const __nv_bfloat16* pAh = Agh + (size_t)(row0 + ar) * lda + akh;
    const __nv_bfloat16* pBh = Bgh + (size_t)bk * ldb + col0 + bns;
    const __nv_bfloat16* pBl = Bgl + (size_t)bk * ldb + col0 + bns;
    int aoff = ar * APADS + akh;
    int boff = bk * BPADS + bns;

    // prologue: tile 0 -> buffer 0
    {
        uint4 a0 = ((const uint4*)pAh)[0], a1 = ((const uint4*)pAh)[1];
        uint4 b0 = ((const uint4*)pBh)[0], b1 = ((const uint4*)pBh)[1];
        uint4 c0 = ((const uint4*)pBl)[0], c1 = ((const uint4*)pBl)[1];
        ((uint4*)(Abuf[0] + aoff))[0] = a0; ((uint4*)(Abuf[0] + aoff))[1] = a1;
        ((uint4*)(Bhb[0]  + boff))[0] = b0; ((uint4*)(Bhb[0]  + boff))[1] = b1;
        ((uint4*)(Blb[0]  + boff))[0] = c0; ((uint4*)(Blb[0]  + boff))[1] = c1;
    }
    __syncthreads();

    int nIter = Kp / GBK;
    for (int it = 0; it < nIter; it++) {
        int cur = it & 1, nxt = cur ^ 1;
        bool has = (it + 1 < nIter);
        uint4 rA0, rA1, rB0, rB1, rC0, rC1;
        if (has) {
            int k1 = (it + 1) * GBK;
            rA0 = ((const uint4*)(pAh + k1))[0];
            rA1 = ((const uint4*)(pAh + k1))[1];
            rB0 = ((const uint4*)(pBh + (size_t)k1 * ldb))[0];
            rB1 = ((const uint4*)(pBh + (size_t)k1 * ldb))[1];
            rC0 = ((const uint4*)(pBl + (size_t)k1 * ldb))[0];
            rC1 = ((const uint4*)(pBl + (size_t)k1 * ldb))[1];
        }
        const __nv_bfloat16* As = Abuf[cur];
        const __nv_bfloat16* Bhs = Bhb[cur];
        const __nv_bfloat16* Bls = Blb[cur];
#pragma unroll
        for (int ks = 0; ks < GBK; ks += 16) {
            wmma::fragment<wmma::matrix_b, 16, 16, 16, __nv_bfloat16, wmma::row_major> bh[2], bl[2];
            wmma::load_matrix_sync(bh[0], Bhs + ks * BPADS + wn * 32,      BPADS);
            wmma::load_matrix_sync(bh[1], Bhs + ks * BPADS + wn * 32 + 16, BPADS);
            wmma::load_matrix_sync(bl[0], Bls + ks * BPADS + wn * 32,      BPADS);
            wmma::load_matrix_sync(bl[1], Bls + ks * BPADS + wn * 32 + 16, BPADS);
#pragma unroll
            for (int im = 0; im < 4; im++) {
                wmma::fragment<wmma::matrix_a, 16, 16, 16, __nv_bfloat16, wmma::row_major> ah;
                wmma::load_matrix_sync(ah, As + (wm * 64 + im * 16) * APADS + ks, APADS);
#pragma unroll
                for (int j = 0; j < 2; j++) {
                    wmma::mma_sync(acc[im][j], ah, bh[j], acc[im][j]);
                    wmma::mma_sync(acc[im][j], ah, bl[j], acc[im][j]);
                }
            }
        }
        if (has) {
            ((uint4*)(Abuf[nxt] + aoff))[0] = rA0; ((uint4*)(Abuf[nxt] + aoff))[1] = rA1;
            ((uint4*)(Bhb[nxt]  + boff))[0] = rB0; ((uint4*)(Bhb[nxt]  + boff))[1] = rB1;
            ((uint4*)(Blb[nxt]  + boff))[0] = rC0; ((uint4*)(Blb[nxt]  + boff))[1] = rC1;
        }
        __syncthreads();
    }

    // staged epilogue (round-1 semantics, full guards); Cs overlays tile buffers (synced)
    for (int ph = 0; ph < 2; ph++) {
        if (wm == ph) {
#pragma unroll
            for (int im = 0; im < 4; im++)
#pragma unroll
                for (int j = 0; j < 2; j++)
                    wmma::store_matrix_sync(Cs + (im * 16) * CPADS + wn * 32 + j * 16,
                                            acc[im][j], CPADS, wmma::mem_row_major);
        }
        __syncthreads();
        for (int e = tid; e < 64 * 128; e += 256) {
            int rr = e >> 7, cc = e & 127;
            int gr = row0 + ph * 64 + rr, gc = col0 + cc;
            if (gr < M && gc < N) {
                float v = Cs[rr * CPADS + cc];
                if (bias) v += bias[gc];
                size_t ix = (size_t)gr * N + gc;
                if (accum) v += C[ix];
                if (relu) v = fmaxf(v, 0.f);
                C[ix] = v;
            }
        }
        __syncthreads();
    }
}

// ---------------- GRU gating + h = mem_upd + node_features -> bf16 plane ----------------
__global__ void k_gate(const float* __restrict__ mem, const float* __restrict__ nf, int Nn) {
    int idx = blockIdx.x * blockDim.x + threadIdx.x;
    if (idx >= NPAD * KP_S) return;
    int n = idx / KP_S, d = idx - n * KP_S;
    float out = 0.f;
    if (n < Nn && d < MEMD) {
        size_t mi = (size_t)n * MEMD + d;
        float mv = mem[mi];
        float hv;
        if (g_lastpos[n] >= 0) {
            const float* gi = g_GI + (size_t)n * G3;
            const float* gh = g_GH + (size_t)n * G3;
            float r = 1.f / (1.f + expf(-(gi[d] + gh[d])));
            float z = 1.f / (1.f + expf(-(gi[MEMD + d] + gh[MEMD + d])));
            float g = tanhf(gi[2 * MEMD + d] + r * gh[2 * MEMD + d]);
            hv = (1.f - z) * g + z * mv;
        } else {
            hv = mv;
        }
        out = hv + nf[mi];
    }
    g_hh[idx] = __float2bfloat16(out);
}

// ---------------- temporal attention -> bf16 agg plane ----------------
__global__ void k_attn(const float* __restrict__ Wk_full, const float* __restrict__ Wv_full,
                       const int* __restrict__ nbi, const float* __restrict__ nts,
                       const float* __restrict__ tw, const float* __restrict__ tb,
                       const float* __restrict__ ts, int Nn, int E) {
    int n = blockIdx.x;
    int tid = threadIdx.x;
    if (n >= Nn) {
        __nv_bfloat16 z = __float2bfloat16(0.f);
        for (int d = tid; d < KP_S; d += blockDim.x)
            g_aggh[(size_t)n * KP_S + d] = z;
        return;
    }
    __shared__ float s_q[MEMD];
    __shared__ float s_c[2 * TDD];
    __shared__ float s_te[KNB * TDD];
    __shared__ float s_sc[2 * KNB];
    __shared__ float s_at[2 * KNB];
    __shared__ float s_wt[2 * TDD];
    __shared__ int s_nb[KNB];

    const float* Wk2 = Wk_full + MEMD * MEMD;
    const float* Wv2 = Wv_full + MEMD * MEMD;
    float t_now = __ldg(&ts[E - 1]);

    if (tid < KNB) s_nb[tid] = nbi[(size_t)n * KNB + tid];
    for (int i = tid; i < MEMD; i += blockDim.x)
        s_q[i] = g_QKV[(size_t)n * G3 + i] + g_qconst[i];
    __syncthreads();

    for (int j = tid; j < 2 * TDD; j += blockDim.x) {
        int hh = j / TDD, t = j - hh * TDD;
        const float* wr = Wk2 + (size_t)t * MEMD + hh * DHD;
        const float* qq = s_q + hh * DHD;
        float s = 0.f;
        for (int d = 0; d < DHD; d++) s += wr[d] * qq[d];
        s_c[j] = s;
    }
    for (int j = tid; j < KNB * TDD; j += blockDim.x) {
        int k = j / TDD, t = j - k * TDD;
        float dt = t_now - nts[(size_t)n * KNB + k];
        s_te[j] = cos_acc(dt * tw[t] + tb[t]);
    }
    __syncthreads();

    int wid = tid >> 5, lane = tid & 31;
    for (int p = wid; p < 2 * KNB; p += 4) {
        int k = p >> 1, hh = p & 1;
        const float* kr = g_QKV + (size_t)s_nb[k] * G3 + MEMD + hh * DHD;
        const float* qq = s_q + hh * DHD;
        float s = 0.f;
        for (int d = lane; d < DHD; d += 32) s += qq[d] * kr[d];
        const float* cc = s_c + hh * TDD;
        const float* te = s_te + k * TDD;
        for (int t = lane; t < TDD; t += 32) s += cc[t] * te[t];
        for (int o = 16; o; o >>= 1) s += __shfl_down_sync(0xffffffffu, s, o);
        if (lane == 0) s_sc[hh * KNB + k] = s * 0.10783277320343841f;  // 1/sqrt(86)
    }
    __syncthreads();

    if (tid < 2) {
        float mx = -1e30f;
        for (int k = 0; k < KNB; k++) mx = fmaxf(mx, s_sc[tid * KNB + k]);
        float sum = 0.f;
        for (int k = 0; k < KNB; k++) {
            float e = expf(s_sc[tid * KNB + k] - mx);
            s_at[tid * KNB + k] = e;
            sum += e;
        }
        float inv = 1.f / sum;
        for (int k = 0; k < KNB; k++) s_at[tid * KNB + k] *= inv;
    }
    __syncthreads();

    for (int j = tid; j < 2 * TDD; j += blockDim.x) {
        int hh = j / TDD, t = j - hh * TDD;
        float s = 0.f;
        for (int k = 0; k < KNB; k++) s += s_at[hh * KNB + k] * s_te[k * TDD + t];
        s_wt[j] = s;
    }
    __syncthreads();

    for (int d = tid; d < MEMD; d += blockDim.x) {
        int hh = d / DHD;
        float s = 0.f;
        for (int k = 0; k < KNB; k++)
            s += s_at[hh * KNB + k] * g_QKV[(size_t)s_nb[k] * G3 + 2 * MEMD + d];
        const float* wv = Wv2 + d;
        const float* wt = s_wt + hh * TDD;
        for (int t = 0; t < TDD; t++) s += wt[t] * wv[(size_t)t * MEMD];
        g_aggh[(size_t)n * KP_S + d] = __float2bfloat16(s);
    }
    __nv_bfloat16 z = __float2bfloat16(0.f);
    for (int d = MEMD + tid; d < KP_S; d += blockDim.x)
        g_aggh[(size_t)n * KP_S + d] = z;
}

// ---------------- T1 fp32 -> bf16 plane ----------------
__global__ void k_t1split(int Nn) {
    int idx = blockIdx.x * blockDim.x + threadIdx.x;
    if (idx >= NPAD * KP_S) return;
    int n = idx / KP_S, d = idx - n * KP_S;
    float v = (n < Nn && d < MEMD) ? g_T1[(size_t)n * MEMD + d] : 0.f;
    g_t1h[idx] = __float2bfloat16(v);
}

// ---------------- deterministic final reduction + classifier ----------------
__global__ void k_reduce1(int Nn) {
    int b = blockIdx.x, c = threadIdx.x;
    if (c >= MEMD) return;
    float s = 0.f;
    for (int r = 1 + b; r < Nn; r += RB) s += g_emb[(size_t)r * MEMD + c];
    g_partial[b * MEMD + c] = s;
}

__global__ void k_final(const float* __restrict__ fc2w, const float* __restrict__ fc2b,
                        float* __restrict__ out, int Nn) {
    __shared__ float tm[MEMD];
    int c = threadIdx.x;
    if (c < MEMD) {
        float s = 0.f;
        for (int b = 0; b < RB; b++) s += g_partial[b * MEMD + c];
        tm[c] = tanhf(s / (float)(Nn - 1));
    }
    __syncthreads();
    if (c == 0) {
        float l0 = fc2b[0], l1 = fc2b[1];
        for (int i = 0; i < MEMD; i++) {
            l0 += tm[i] * fc2w[i * 2 + 0];
            l1 += tm[i] * fc2w[i * 2 + 1];
        }
        float mx = fmaxf(l0, l1);
        float e0 = expf(l0 - mx), e1 = expf(l1 - mx);
        float inv = 1.f / (e0 + e1);
        out[0] = e0 * inv;
        out[1] = e1 * inv;
    }
}

// ---------------- host orchestration ----------------
extern "C" void kernel_launch(void* const* d_in, const int* in_sizes, int n_in,
                              void* d_out, int out_size) {
    const float* node_features = (const float*)d_in[0];
    const float* memory        = (const float*)d_in[1];
    const float* last_update   = (const float*)d_in[2];
    const float* timestamps    = (const float*)d_in[3];
    const float* edge_features = (const float*)d_in[4];
    const float* neighbor_ts   = (const float*)d_in[5];
    const float* time_w        = (const float*)d_in[6];
    const float* time_b        = (const float*)d_in[7];
    const float* gru_Wi        = (const float*)d_in[8];
    const float* gru_Wh        = (const float*)d_in[9];
    const float* gru_bi        = (const float*)d_in[10];
    const float* gru_bh        = (const float*)d_in[11];
    const float* Wq            = (const float*)d_in[12];
    const float* Wk            = (const float*)d_in[13];
    const float* Wv            = (const float*)d_in[14];
    const float* W1            = (const float*)d_in[15];
    const float* b1            = (const float*)d_in[16];
    const float* W2            = (const float*)d_in[17];
    const float* b2            = (const float*)d_in[18];
    const float* fc2_w         = (const float*)d_in[19];
    const float* fc2_b         = (const float*)d_in[20];
    const int*   sources       = (const int*)d_in[21];
    const int*   destinations  = (const int*)d_in[22];
    const int*   neighbor_idx  = (const int*)d_in[23];

    int N = in_sizes[0] / FEATD;
    int E = in_sizes[3];
    int MtRows = NPAD / 128;

    static int s_attr_done = 0;
    if (!s_attr_done) {
        cudaFuncSetAttribute(k_gemm2, cudaFuncAttributeMaxDynamicSharedMemorySize, SM_TOT);
        s_attr_done = 1;
    }

    __nv_bfloat16 *pMh, *pMemh, *pHh, *pAh, *pT1h;
    __nv_bfloat16 *pWih, *pWil, *pWhh, *pWhl, *pQh, *pQl, *pW1ah, *pW1al, *pW1bh, *pW1bl, *pW2h, *pW2l;
    float *pGI, *pGH, *pQKV, *pT1, *pEmb;
    cudaGetSymbolAddress((void**)&pMh,   g_Mh);
    cudaGetSymbolAddress((void**)&pMemh, g_memh);
    cudaGetSymbolAddress((void**)&pHh,   g_hh);
    cudaGetSymbolAddress((void**)&pAh,   g_aggh);
    cudaGetSymbolAddress((void**)&pT1h,  g_t1h);
    cudaGetSymbolAddress((void**)&pWih,  g_BWih);
    cudaGetSymbolAddress((void**)&pWil,  g_BWil);
    cudaGetSymbolAddress((void**)&pWhh,  g_BWhh);
    cudaGetSymbolAddress((void**)&pWhl,  g_BWhl);
    cudaGetSymbolAddress((void**)&pQh,   g_BQh);
    cudaGetSymbolAddress((void**)&pQl,   g_BQl);
    cudaGetSymbolAddress((void**)&pW1ah, g_BW1ah);
    cudaGetSymbolAddress((void**)&pW1al, g_BW1al);
    cudaGetSymbolAddress((void**)&pW1bh, g_BW1bh);
    cudaGetSymbolAddress((void**)&pW1bl, g_BW1bl);
    cudaGetSymbolAddress((void**)&pW2h,  g_BW2h);
    cudaGetSymbolAddress((void**)&pW2l,  g_BW2l);
    cudaGetSymbolAddress((void**)&pGI,   g_GI);
    cudaGetSymbolAddress((void**)&pGH,   g_GH);
    cudaGetSymbolAddress((void**)&pQKV,  g_QKV);
    cudaGetSymbolAddress((void**)&pT1,   g_T1);
    cudaGetSymbolAddress((void**)&pEmb,  g_emb);

    // launch order: GI GEMM at my-index 3 (profiled by ncu -s 5)
    k_prep_wi_init<<<(KP_M * NP_G + 255) / 256, 256>>>(gru_Wi, N);          // 0
    k_scatter<<<(E + 255) / 256, 256>>>(sources, destinations, E);          // 1
    k_build_m<<<NPAD, 128>>>(memory, last_update, timestamps, edge_features,
                             time_w, time_b, sources, destinations, N, E);  // 2
    k_gemm2<<<dim3(5, MtRows), 256, SM_TOT>>>(pMh, KP_M, pWih, pWil, NP_G,
                                              gru_bi, pGI, N, G3, KP_M, 0, 0);  // 3
    k_memconv<<<(NPAD * KP_S + 255) / 256, 256>>>(memory, N);               // 4
    k_prep_wh<<<(KP_S * NP_G + 255) / 256, 256>>>(gru_Wh);                  // 5
    k_gemm2<<<dim3(5, MtRows), 256, SM_TOT>>>(pMemh, KP_S, pWhh, pWhl, NP_G,
                                              gru_bh, pGH, N, G3, KP_S, 0, 0);
    k_gate<<<(NPAD * KP_S + 255) / 256, 256>>>(memory, node_features, N);

    // QKV = h @ Bqkv
    k_prep_qkv<<<(KP_S * NP_G + 255) / 256, 256>>>(Wq, Wk, Wv);
    k_gemm2<<<dim3(5, MtRows), 256, SM_TOT>>>(pHh, KP_S, pQh, pQl, NP_G,
                                              nullptr, pQKV, N, G3, KP_S, 0, 0);

    // attention
    k_prep_qconst<<<1, 192>>>(Wq, time_b);
    k_attn<<<NPAD, 128>>>(Wk, Wv, neighbor_idx, neighbor_ts, time_w, time_b,
                          timestamps, N, E);

    // MLP
    k_prep_w1<<<(KP_S * NP_S + 255) / 256, 256>>>(W1);
    k_prep_w2<<<(KP_S * NP_S + 255) / 256, 256>>>(W2);
    k_gemm2<<<dim3(2, MtRows), 256, SM_TOT>>>(pHh, KP_S, pW1ah, pW1al, NP_S,
                                              b1, pT1, N, MEMD, KP_S, 0, 0);
    k_gemm2<<<dim3(2, MtRows), 256, SM_TOT>>>(pAh, KP_S, pW1bh, pW1bl, NP_S,
                                              nullptr, pT1, N, MEMD, KP_S, 1, 1);
    k_t1split<<<(NPAD * KP_S + 255) / 256, 256>>>(N);
    k_gemm2<<<dim3(2, MtRows), 256, SM_TOT>>>(pT1h, KP_S, pW2h, pW2l, NP_S,
                                              b2, pEmb, N, MEMD, KP_S, 0, 0);

    // classifier head
    k_reduce1<<<RB, 192>>>(N);
    k_final<<<1, 192>>>(fc2_w, fc2_b, (float*)d_out, N);
}

// round 11
// speedup vs baseline: 1.6933x; 1.2365x over previous
#include <cuda_runtime.h>
#include <cuda_bf16.h>
#include <mma.h>
#include <math.h>

using namespace nvcuda;

#define MEMD 172
#define FEATD 172
#define TDD 100
#define KNB 10
#define DHD 86
#define MSGD 616          // 2*MEM + FEAT + TD
#define G3 516            // 3*MEM
#define NMAX 100000
#define NPAD 100096       // ceil(100000/128)*128 rows for A-operand buffers
#define RB 256

// padded K strides for bf16 operand buffers
#define KP_M 640          // 616 -> 640
#define KP_S 192          // 172 -> 192
// padded N strides for B operand buffers
#define NP_G 640          // 516 -> 640 (GI / GH)
#define NP_Q 768          // 516 + 200 score cols -> 768 (QKV extended)
#define NP_S 256          // 172 -> 256
#define WT_K 256          // wt-GEMM K (200 -> 256)

// ---------------- device scratch ----------------
__device__ int   g_lastpos[NMAX];
// A-operand planes (single bf16 hi; explicitly zero-padded by producers)
__device__ __nv_bfloat16 g_Mh[(size_t)NPAD * KP_M];
__device__ __nv_bfloat16 g_memh[(size_t)NPAD * KP_S];
__device__ __nv_bfloat16 g_hh[(size_t)NPAD * KP_S];
__device__ __nv_bfloat16 g_aggh[(size_t)NPAD * KP_S];
__device__ __nv_bfloat16 g_t1h[(size_t)NPAD * KP_S];
__device__ __nv_bfloat16 g_wtb[(size_t)NPAD * WT_K];     // attention-weighted tenc (A operand)
// B-operand split planes [Kp][Np], explicitly zero-padded (weights: hi+lo)
__device__ __nv_bfloat16 g_BWih[KP_M * NP_G];
__device__ __nv_bfloat16 g_BWil[KP_M * NP_G];
__device__ __nv_bfloat16 g_BWhh[KP_S * NP_G];
__device__ __nv_bfloat16 g_BWhl[KP_S * NP_G];
__device__ __nv_bfloat16 g_BQh[KP_S * NP_Q];
__device__ __nv_bfloat16 g_BQl[KP_S * NP_Q];
__device__ __nv_bfloat16 g_BVh[WT_K * 256];              // block-diag Wv2 (rows k=hh*100+t)
__device__ __nv_bfloat16 g_BVl[WT_K * 256];
__device__ __nv_bfloat16 g_BW1ah[KP_S * NP_S];
__device__ __nv_bfloat16 g_BW1al[KP_S * NP_S];
__device__ __nv_bfloat16 g_BW1bh[KP_S * NP_S];
__device__ __nv_bfloat16 g_BW1bl[KP_S * NP_S];
__device__ __nv_bfloat16 g_BW2h[KP_S * NP_S];
__device__ __nv_bfloat16 g_BW2l[KP_S * NP_S];
// fp32 GEMM outputs
__device__ float g_GI[(size_t)NMAX * G3];
__device__ float g_GH[(size_t)NMAX * G3];
__device__ float g_QKV[(size_t)NMAX * NP_Q];             // [q|k|v|score-c] per node
__device__ float g_aggF[(size_t)NPAD * KP_S];            // fp32 agg accumulator
__device__ float g_T1[(size_t)NMAX * MEMD];
__device__ float g_emb[(size_t)NMAX * MEMD];
__device__ float g_qconst[MEMD];
__device__ float g_const2[2 * TDD];
__device__ float g_partial[RB * MEMD];

// robust cos for large args (fast-math-safe): fp64 2*pi range reduction
__device__ __forceinline__ float cos_acc(float x) {
    double xd = (double)x;
    double q = rint(xd * 0.15915494309189535);
    float r = (float)(xd - q * 6.283185307179586);
    return cosf(r);
}

__device__ __forceinline__ void split2(float x, __nv_bfloat16* hi, __nv_bfloat16* lo) {
    __nv_bfloat16 h = __float2bfloat16(x);
    *hi = h;
    *lo = __float2bfloat16(x - __bfloat162float(h));
}

// ---------------- prep kernels ----------------
__global__ void k_prep_wi_init(const float* __restrict__ Wi, int N) {
    int idx = blockIdx.x * blockDim.x + threadIdx.x;
    if (idx < N) g_lastpos[idx] = -1;
    if (idx < KP_M * NP_G) {
        int k = idx / NP_G, n = idx - k * NP_G;
        float v = (k < MSGD && n < G3) ? Wi[n * MSGD + k] : 0.f;
        split2(v, &g_BWih[idx], &g_BWil[idx]);
    }
}

__global__ void k_scatter(const int* __restrict__ src, const int* __restrict__ dst, int E) {
    int e = blockIdx.x * blockDim.x + threadIdx.x;
    if (e < E) {
        atomicMax(&g_lastpos[src[e]], e);
        atomicMax(&g_lastpos[dst[e]], E + e);
    }
}

__global__ void k_prep_wh(const float* __restrict__ Wh) {
    int idx = blockIdx.x * blockDim.x + threadIdx.x;
    if (idx < KP_S * NP_G) {
        int k = idx / NP_G, n = idx - k * NP_G;
        float v = (k < MEMD && n < G3) ? Wh[n * MEMD + k] : 0.f;
        split2(v, &g_BWhh[idx], &g_BWhl[idx]);
    }
}

// extended QKV B: cols [0,516) = [Wq1|Wk1|Wv1]; cols [516,716) = Wc (fused score
// weights: Wc[k][516+hh*100+t] = sum_d Wq1[k][hh*86+d] * Wk2[t][hh*86+d]); rest 0.
__global__ void k_prep_qkv(const float* __restrict__ Wq, const float* __restrict__ Wk,
                           const float* __restrict__ Wv) {
    int idx = blockIdx.x * blockDim.x + threadIdx.x;
    if (idx >= KP_S * NP_Q) return;
    int k = idx / NP_Q, n = idx - k * NP_Q;
    float v = 0.f;
    if (k < MEMD) {
        if (n < G3) {
            int sel = n / MEMD, jj = n - sel * MEMD;
            const float* W = (sel == 0) ? Wq : ((sel == 1) ? Wk : Wv);
            v = W[k * MEMD + jj];
        } else if (n < G3 + 2 * TDD) {
            int j = n - G3;
            int hh = j / TDD, t = j - hh * TDD;
            const float* wq = Wq + (size_t)k * MEMD + hh * DHD;
            const float* wk2 = Wk + (size_t)(MEMD + t) * MEMD + hh * DHD;
            float s = 0.f;
            for (int d = 0; d < DHD; d++) s += wq[d] * wk2[d];
            v = s;
        }
    }
    split2(v, &g_BQh[idx], &g_BQl[idx]);
}

// block-diagonal Wv2: B[k=hh*100+t][d] = (d/86 == hh) ? Wv2[t][d] : 0; [256][256]
__global__ void k_prep_bv(const float* __restrict__ Wv) {
    int idx = blockIdx.x * blockDim.x + threadIdx.x;
    if (idx >= WT_K * 256) return;
    int kk = idx / 256, d = idx - kk * 256;
    float v = 0.f;
    if (kk < 2 * TDD && d < MEMD) {
        int hh = kk / TDD, t = kk - hh * TDD;
        if (d / DHD == hh) v = Wv[(size_t)(MEMD + t) * MEMD + d];
    }
    split2(v, &g_BVh[idx], &g_BVl[idx]);
}

__global__ void k_prep_w1(const float* __restrict__ W1) {
    int idx = blockIdx.x * blockDim.x + threadIdx.x;
    if (idx < KP_S * NP_S) {
        int k = idx / NP_S, n = idx - k * NP_S;
        float va = 0.f, vb = 0.f;
        if (k < MEMD && n < MEMD) {
            va = W1[k * MEMD + n];
            vb = W1[(MEMD + k) * MEMD + n];
        }
        split2(va, &g_BW1ah[idx], &g_BW1al[idx]);
        split2(vb, &g_BW1bh[idx], &g_BW1bl[idx]);
    }
}

__global__ void k_prep_w2(const float* __restrict__ W2) {
    int idx = blockIdx.x * blockDim.x + threadIdx.x;
    if (idx < KP_S * NP_S) {
        int k = idx / NP_S, n = idx - k * NP_S;
        float v = (k < MEMD && n < MEMD) ? W2[k * MEMD + n] : 0.f;
        split2(v, &g_BW2h[idx], &g_BW2l[idx]);
    }
}

// qconst (q-side tenc const) then const2 (score const): const2[hh*100+t] = Wk2[t,hh]·qconst[hh]
__global__ void k_prep_qconst(const float* __restrict__ Wq, const float* __restrict__ Wk,
                              const float* __restrict__ tb) {
    __shared__ float qc[MEMD];
    int j = threadIdx.x;
    if (j < MEMD) {
        float s = 0.f;
        for (int t = 0; t < TDD; t++)
            s += cos_acc(tb[t]) * Wq[(MEMD + t) * MEMD + j];
        qc[j] = s;
        g_qconst[j] = s;
    }
    __syncthreads();
    if (j < 2 * TDD) {
        int hh = j / TDD, t = j - hh * TDD;
        const float* wk2 = Wk + (size_t)(MEMD + t) * MEMD + hh * DHD;
        float s = 0.f;
        for (int d = 0; d < DHD; d++) s += wk2[d] * qc[hh * DHD + d];
        g_const2[j] = s;
    }
}

__global__ void k_memconv(const float* __restrict__ mem, int Nn) {
    int idx = blockIdx.x * blockDim.x + threadIdx.x;
    if (idx >= NPAD * KP_S) return;
    int n = idx / KP_S, d = idx - n * KP_S;
    float v = (n < Nn && d < MEMD) ? mem[(size_t)n * MEMD + d] : 0.f;
    g_memh[idx] = __float2bfloat16(v);
}

// ---------------- build selected message matrix -> bf16 plane [NPAD][640] ----------------
__global__ void k_build_m(const float* __restrict__ mem, const float* __restrict__ lu,
                          const float* __restrict__ ts, const float* __restrict__ ef,
                          const float* __restrict__ tw, const float* __restrict__ tb,
                          const int* __restrict__ src, const int* __restrict__ dst,
                          int Nn, int E) {
    int n = blockIdx.x;
    int tid = threadIdx.x;
    __nv_bfloat16* rh = g_Mh + (size_t)n * KP_M;
    __shared__ int s_a, s_b, s_e, s_has;
    __shared__ float s_dt;
    if (tid == 0) {
        int p = (n < Nn) ? g_lastpos[n] : -1;
        if (p < 0) {
            s_has = 0;
        } else {
            s_has = 1;
            int e, a, b;
            if (p < E) { e = p;     a = src[e]; b = dst[e]; }
            else       { e = p - E; a = dst[e]; b = src[e]; }
            s_e = e; s_a = a; s_b = b;
            s_dt = ts[e] - lu[a];
        }
    }
    __syncthreads();
    if (!s_has) {
        __nv_bfloat16 z = __float2bfloat16(0.f);
        for (int i = tid; i < KP_M; i += blockDim.x) rh[i] = z;
        return;
    }
    int a = s_a, b = s_b, e = s_e;
    float dt = s_dt;
    for (int i = tid; i < KP_M; i += blockDim.x) {
        float v = 0.f;
        if (i < MEMD)                  v = mem[(size_t)a * MEMD + i];
        else if (i < 2 * MEMD)         v = mem[(size_t)b * MEMD + (i - MEMD)];
        else if (i < 2 * MEMD + FEATD) v = ef[(size_t)e * FEATD + (i - 2 * MEMD)];
        else if (i < MSGD) { int t = i - (2 * MEMD + FEATD); v = cos_acc(dt * tw[t] + tb[t]); }
        rh[i] = __float2bfloat16(v);
    }
}

// ---------------- 2-product bf16 wmma GEMM: C (+)= Ah @ (Bh + Bl) ------------------------
#define GBK 32
#define APADS 40
#define BPADS 136
#define CPADS 132
#define SM_A0   0
#define SM_A1   10240
#define SM_BH0  20480
#define SM_BL0  29184
#define SM_BH1  37888
#define SM_BL1  46592
#define SM_TOT  55296

__global__ __launch_bounds__(256, 2) void k_gemm2(
        const __nv_bfloat16* __restrict__ Agh, int lda,
        const __nv_bfloat16* __restrict__ Bgh, const __nv_bfloat16* __restrict__ Bgl, int ldb,
        const float* __restrict__ bias, float* __restrict__ C,
        int M, int N, int Kp, int accum, int relu) {
    extern __shared__ __align__(16) unsigned char sraw[];
    __nv_bfloat16* Abuf[2] = { (__nv_bfloat16*)(sraw + SM_A0),  (__nv_bfloat16*)(sraw + SM_A1)  };
    __nv_bfloat16* Bhb[2]  = { (__nv_bfloat16*)(sraw + SM_BH0), (__nv_bfloat16*)(sraw + SM_BH1) };
    __nv_bfloat16* Blb[2]  = { (__nv_bfloat16*)(sraw + SM_BL0), (__nv_bfloat16*)(sraw + SM_BL1) };
    float* Cs = (float*)sraw;

    int tid = threadIdx.x;
    int w = tid >> 5;
    int wm = w >> 2, wn = w & 3;
    int row0 = blockIdx.y * 128;
    int col0 = blockIdx.x * 128;

    wmma::fragment<wmma::accumulator, 16, 16, 16, float> acc[4][2];
#pragma unroll
    for (int i = 0; i < 4; i++)
#pragma unroll
        for (int j = 0; j < 2; j++) wmma::fill_fragment(acc[i][j], 0.f);

    int ar = tid >> 1, akh = (tid & 1) * 16;
    int bk = tid >> 3, bns = (tid & 7) * 16;
    const __nv_bfloat16* pAh = Agh + (size_t)(row0 + ar) * lda + akh;
    const __nv_bfloat16* pBh = Bgh + (size_t)bk * ldb + col0 + bns;
    const __nv_bfloat16* pBl = Bgl + (size_t)bk * ldb + col0 + bns;
    int aoff = ar * APADS + akh;
    int boff = bk * BPADS + bns;

    {
        uint4 a0 = ((const uint4*)pAh)[0], a1 = ((const uint4*)pAh)[1];
        uint4 b0 = ((const uint4*)pBh)[0], b1 = ((const uint4*)pBh)[1];
        uint4 c0 = ((const uint4*)pBl)[0], c1 = ((const uint4*)pBl)[1];
        ((uint4*)(Abuf[0] + aoff))[0] = a0; ((uint4*)(Abuf[0] + aoff))[1] = a1;
        ((uint4*)(Bhb[0]  + boff))[0] = b0; ((uint4*)(Bhb[0]  + boff))[1] = b1;
        ((uint4*)(Blb[0]  + boff))[0] = c0; ((uint4*)(Blb[0]  + boff))[1] = c1;
    }
    __syncthreads();

    int nIter = Kp / GBK;
    for (int it = 0; it < nIter; it++) {
        int cur = it & 1, nxt = cur ^ 1;
        bool has = (it + 1 < nIter);
        uint4 rA0, rA1, rB0, rB1, rC0, rC1;
        if (has) {
            int k1 = (it + 1) * GBK;
            rA0 = ((const uint4*)(pAh + k1))[0];
            rA1 = ((const uint4*)(pAh + k1))[1];
            rB0 = ((const uint4*)(pBh + (size_t)k1 * ldb))[0];
            rB1 = ((const uint4*)(pBh + (size_t)k1 * ldb))[1];
            rC0 = ((const uint4*)(pBl + (size_t)k1 * ldb))[0];
            rC1 = ((const uint4*)(pBl + (size_t)k1 * ldb))[1];
        }
        const __nv_bfloat16* As = Abuf[cur];
        const __nv_bfloat16* Bhs = Bhb[cur];
        const __nv_bfloat16* Bls = Blb[cur];
#pragma unroll
        for (int ks = 0; ks < GBK; ks += 16) {
            wmma::fragment<wmma::matrix_b, 16, 16, 16, __nv_bfloat16, wmma::row_major> bh[2], bl[2];
            wmma::load_matrix_sync(bh[0], Bhs + ks * BPADS + wn * 32,      BPADS);
            wmma::load_matrix_sync(bh[1], Bhs + ks * BPADS + wn * 32 + 16, BPADS);
            wmma::load_matrix_sync(bl[0], Bls + ks * BPADS + wn * 32,      BPADS);
            wmma::load_matrix_sync(bl[1], Bls + ks * BPADS + wn * 32 + 16, BPADS);
#pragma unroll
            for (int im = 0; im < 4; im++) {
                wmma::fragment<wmma::matrix_a, 16, 16, 16, __nv_bfloat16, wmma::row_major> ah;
                wmma::load_matrix_sync(ah, As + (wm * 64 + im * 16) * APADS + ks, APADS);
#pragma unroll
                for (int j = 0; j < 2; j++) {
                    wmma::mma_sync(acc[im][j], ah, bh[j], acc[im][j]);
                    wmma::mma_sync(acc[im][j], ah, bl[j], acc[im][j]);
                }
            }
        }
        if (has) {
            ((uint4*)(Abuf[nxt] + aoff))[0] = rA0; ((uint4*)(Abuf[nxt] + aoff))[1] = rA1;
            ((uint4*)(Bhb[nxt]  + boff))[0] = rB0; ((uint4*)(Bhb[nxt]  + boff))[1] = rB1;
            ((uint4*)(Blb[nxt]  + boff))[0] = rC0; ((uint4*)(Blb[nxt]  + boff))[1] = rC1;
        }
        __syncthreads();
    }

    for (int ph = 0; ph < 2; ph++) {
        if (wm == ph) {
#pragma unroll
            for (int im = 0; im < 4; im++)
#pragma unroll
                for (int j = 0; j < 2; j++)
                    wmma::store_matrix_sync(Cs + (im * 16) * CPADS + wn * 32 + j * 16,
                                            acc[im][j], CPADS, wmma::mem_row_major);
        }
        __syncthreads();
        for (int e = tid; e < 64 * 128; e += 256) {
            int rr = e >> 7, cc = e & 127;
            int gr = row0 + ph * 64 + rr, gc = col0 + cc;
            if (gr < M && gc < N) {
                float v = Cs[rr * CPADS + cc];
                if (bias) v += bias[gc];
                size_t ix = (size_t)gr * N + gc;
                if (accum) v += C[ix];
                if (relu) v = fmaxf(v, 0.f);
                C[ix] = v;
            }
        }
        __syncthreads();
    }
}

// ---------------- GRU gating + h = mem_upd + node_features -> bf16 plane ----------------
__global__ void k_gate(const float* __restrict__ mem, const float* __restrict__ nf, int Nn) {
    int idx = blockIdx.x * blockDim.x + threadIdx.x;
    if (idx >= NPAD * KP_S) return;
    int n = idx / KP_S, d = idx - n * KP_S;
    float out = 0.f;
    if (n < Nn && d < MEMD) {
        size_t mi = (size_t)n * MEMD + d;
        float mv = mem[mi];
        float hv;
        if (g_lastpos[n] >= 0) {
            const float* gi = g_GI + (size_t)n * G3;
            const float* gh = g_GH + (size_t)n * G3;
            float r = 1.f / (1.f + expf(-(gi[d] + gh[d])));
            float z = 1.f / (1.f + expf(-(gi[MEMD + d] + gh[MEMD + d])));
            float g = tanhf(gi[2 * MEMD + d] + r * gh[2 * MEMD + d]);
            hv = (1.f - z) * g + z * mv;
        } else {
            hv = mv;
        }
        out = hv + nf[mi];
    }
    g_hh[idx] = __float2bfloat16(out);
}

// ---------------- temporal attention (weight terms pre-GEMMed) ----------------
// reads: QKV[q | k | v | c-score], const2; computes te, softmax, neighbor-v gather;
// writes: wt plane (bf16 A-operand for the Wv2 GEMM) + fp32 neighbor-agg into g_aggF.
__global__ void k_attn(const int* __restrict__ nbi, const float* __restrict__ nts,
                       const float* __restrict__ tw, const float* __restrict__ tb,
                       const float* __restrict__ ts, int Nn, int E) {
    int n = blockIdx.x;
    int tid = threadIdx.x;
    if (n >= Nn) {   // pad rows: zero wt + aggF
        __nv_bfloat16 z = __float2bfloat16(0.f);
        for (int d = tid; d < WT_K; d += blockDim.x) g_wtb[(size_t)n * WT_K + d] = z;
        for (int d = tid; d < KP_S; d += blockDim.x) g_aggF[(size_t)n * KP_S + d] = 0.f;
        return;
    }
    __shared__ float s_q[MEMD];
    __shared__ float s_c[2 * TDD];
    __shared__ float s_te[KNB * TDD];
    __shared__ float s_sc[2 * KNB];
    __shared__ float s_at[2 * KNB];
    __shared__ int s_nb[KNB];

    const float* qrow = g_QKV + (size_t)n * NP_Q;
    float t_now = __ldg(&ts[E - 1]);

    if (tid < KNB) s_nb[tid] = nbi[(size_t)n * KNB + tid];
    for (int i = tid; i < MEMD; i += blockDim.x)
        s_q[i] = qrow[i] + g_qconst[i];
    for (int j = tid; j < 2 * TDD; j += blockDim.x)
        s_c[j] = qrow[G3 + j] + g_const2[j];
    for (int j = tid; j < KNB * TDD; j += blockDim.x) {
        int k = j / TDD, t = j - k * TDD;
        float dt = t_now - nts[(size_t)n * KNB + k];
        s_te[j] = cos_acc(dt * tw[t] + tb[t]);
    }
    __syncthreads();

    int wid = tid >> 5, lane = tid & 31;
    for (int p = wid; p < 2 * KNB; p += 4) {
        int k = p >> 1, hh = p & 1;
        const float* kr = g_QKV + (size_t)s_nb[k] * NP_Q + MEMD + hh * DHD;
        const float* qq = s_q + hh * DHD;
        float s = 0.f;
        for (int d = lane; d < DHD; d += 32) s += qq[d] * kr[d];
        const float* cc = s_c + hh * TDD;
        const float* te = s_te + k * TDD;
        for (int t = lane; t < TDD; t += 32) s += cc[t] * te[t];
        for (int o = 16; o; o >>= 1) s += __shfl_down_sync(0xffffffffu, s, o);
        if (lane == 0) s_sc[hh * KNB + k] = s * 0.10783277320343841f;  // 1/sqrt(86)
    }
    __syncthreads();

    if (tid < 2) {
        float mx = -1e30f;
        for (int k = 0; k < KNB; k++) mx = fmaxf(mx, s_sc[tid * KNB + k]);
        float sum = 0.f;
        for (int k = 0; k < KNB; k++) {
            float e = expf(s_sc[tid * KNB + k] - mx);
            s_at[tid * KNB + k] = e;
            sum += e;
        }
        float inv = 1.f / sum;
        for (int k = 0; k < KNB; k++) s_at[tid * KNB + k] *= inv;
    }
    __syncthreads();

    // wt[h,t] = sum_k at[h,k]*te[k,t]  -> bf16 plane (GEMM A operand)
    for (int j = tid; j < WT_K; j += blockDim.x) {
        float s = 0.f;
        if (j < 2 * TDD) {
            int hh = j / TDD, t = j - hh * TDD;
            for (int k = 0; k < KNB; k++) s += s_at[hh * KNB + k] * s_te[k * TDD + t];
        }
        g_wtb[(size_t)n * WT_K + j] = __float2bfloat16(s);
    }

    // neighbor-v gather part of agg -> fp32 (Wv2 GEMM accumulates on top)
    for (int d = tid; d < KP_S; d += blockDim.x) {
        float s = 0.f;
        if (d < MEMD) {
            int hh = d / DHD;
            for (int k = 0; k < KNB; k++)
                s += s_at[hh * KNB + k] * g_QKV[(size_t)s_nb[k] * NP_Q + 2 * MEMD + d];
        }
        g_aggF[(size_t)n * KP_S + d] = s;
    }
}

// ---------------- agg fp32 -> bf16 plane ----------------
__global__ void k_aggsplit(int Nn) {
    int idx = blockIdx.x * blockDim.x + threadIdx.x;
    if (idx >= NPAD * KP_S) return;
    int n = idx / KP_S, d = idx - n * KP_S;
    float v = (n < Nn && d < MEMD) ? g_aggF[idx] : 0.f;
    g_aggh[idx] = __float2bfloat16(v);
}

// ---------------- T1 fp32 -> bf16 plane ----------------
__global__ void k_t1split(int Nn) {
    int idx = blockIdx.x * blockDim.x + threadIdx.x;
    if (idx >= NPAD * KP_S) return;
    int n = idx / KP_S, d = idx - n * KP_S;
    float v = (n < Nn && d < MEMD) ? g_T1[(size_t)n * MEMD + d] : 0.f;
    g_t1h[idx] = __float2bfloat16(v);
}

// ---------------- deterministic final reduction + classifier ----------------
__global__ void k_reduce1(int Nn) {
    int b = blockIdx.x, c = threadIdx.x;
    if (c >= MEMD) return;
    float s = 0.f;
    for (int r = 1 + b; r < Nn; r += RB) s += g_emb[(size_t)r * MEMD + c];
    g_partial[b * MEMD + c] = s;
}

__global__ void k_final(const float* __restrict__ fc2w, const float* __restrict__ fc2b,
                        float* __restrict__ out, int Nn) {
    __shared__ float tm[MEMD];
    int c = threadIdx.x;
    if (c < MEMD) {
        float s = 0.f;
        for (int b = 0; b < RB; b++) s += g_partial[b * MEMD + c];
        tm[c] = tanhf(s / (float)(Nn - 1));
    }
    __syncthreads();
    if (c == 0) {
        float l0 = fc2b[0], l1 = fc2b[1];
        for (int i = 0; i < MEMD; i++) {
            l0 += tm[i] * fc2w[i * 2 + 0];
            l1 += tm[i] * fc2w[i * 2 + 1];
        }
        float mx = fmaxf(l0, l1);
        float e0 = expf(l0 - mx), e1 = expf(l1 - mx);
        float inv = 1.f / (e0 + e1);
        out[0] = e0 * inv;
        out[1] = e1 * inv;
    }
}

// ---------------- host orchestration ----------------
extern "C" void kernel_launch(void* const* d_in, const int* in_sizes, int n_in,
                              void* d_out, int out_size) {
    const float* node_features = (const float*)d_in[0];
    const float* memory        = (const float*)d_in[1];
    const float* last_update   = (const float*)d_in[2];
    const float* timestamps    = (const float*)d_in[3];
    const float* edge_features = (const float*)d_in[4];
    const float* neighbor_ts   = (const float*)d_in[5];
    const float* time_w        = (const float*)d_in[6];
    const float* time_b        = (const float*)d_in[7];
    const float* gru_Wi        = (const float*)d_in[8];
    const float* gru_Wh        = (const float*)d_in[9];
    const float* gru_bi        = (const float*)d_in[10];
    const float* gru_bh        = (const float*)d_in[11];
    const float* Wq            = (const float*)d_in[12];
    const float* Wk            = (const float*)d_in[13];
    const float* Wv            = (const float*)d_in[14];
    const float* W1            = (const float*)d_in[15];
    const float* b1            = (const float*)d_in[16];
    const float* W2            = (const float*)d_in[17];
    const float* b2            = (const float*)d_in[18];
    const float* fc2_w         = (const float*)d_in[19];
    const float* fc2_b         = (const float*)d_in[20];
    const int*   sources       = (const int*)d_in[21];
    const int*   destinations  = (const int*)d_in[22];
    const int*   neighbor_idx  = (const int*)d_in[23];

    int N = in_sizes[0] / FEATD;
    int E = in_sizes[3];
    int MtRows = NPAD / 128;

    static int s_attr_done = 0;
    if (!s_attr_done) {
        cudaFuncSetAttribute(k_gemm2, cudaFuncAttributeMaxDynamicSharedMemorySize, SM_TOT);
        s_attr_done = 1;
    }

    __nv_bfloat16 *pMh, *pMemh, *pHh, *pAh, *pT1h, *pWtb;
    __nv_bfloat16 *pWih, *pWil, *pWhh, *pWhl, *pQh, *pQl, *pBVh, *pBVl;
    __nv_bfloat16 *pW1ah, *pW1al, *pW1bh, *pW1bl, *pW2h, *pW2l;
    float *pGI, *pGH, *pQKV, *pAggF, *pT1, *pEmb;
    cudaGetSymbolAddress((void**)&pMh,   g_Mh);
    cudaGetSymbolAddress((void**)&pMemh, g_memh);
    cudaGetSymbolAddress((void**)&pHh,   g_hh);
    cudaGetSymbolAddress((void**)&pAh,   g_aggh);
    cudaGetSymbolAddress((void**)&pT1h,  g_t1h);
    cudaGetSymbolAddress((void**)&pWtb,  g_wtb);
    cudaGetSymbolAddress((void**)&pWih,  g_BWih);
    cudaGetSymbolAddress((void**)&pWil,  g_BWil);
    cudaGetSymbolAddress((void**)&pWhh,  g_BWhh);
    cudaGetSymbolAddress((void**)&pWhl,  g_BWhl);
    cudaGetSymbolAddress((void**)&pQh,   g_BQh);
    cudaGetSymbolAddress((void**)&pQl,   g_BQl);
    cudaGetSymbolAddress((void**)&pBVh,  g_BVh);
    cudaGetSymbolAddress((void**)&pBVl,  g_BVl);
    cudaGetSymbolAddress((void**)&pW1ah, g_BW1ah);
    cudaGetSymbolAddress((void**)&pW1al, g_BW1al);
    cudaGetSymbolAddress((void**)&pW1bh, g_BW1bh);
    cudaGetSymbolAddress((void**)&pW1bl, g_BW1bl);
    cudaGetSymbolAddress((void**)&pW2h,  g_BW2h);
    cudaGetSymbolAddress((void**)&pW2l,  g_BW2l);
    cudaGetSymbolAddress((void**)&pGI,   g_GI);
    cudaGetSymbolAddress((void**)&pGH,   g_GH);
    cudaGetSymbolAddress((void**)&pQKV,  g_QKV);
    cudaGetSymbolAddress((void**)&pAggF, g_aggF);
    cudaGetSymbolAddress((void**)&pT1,   g_T1);
    cudaGetSymbolAddress((void**)&pEmb,  g_emb);

    // launch order: GI GEMM at my-index 3 (profiled by ncu -s 5)
    k_prep_wi_init<<<(KP_M * NP_G + 255) / 256, 256>>>(gru_Wi, N);
    k_scatter<<<(E + 255) / 256, 256>>>(sources, destinations, E);
    k_build_m<<<NPAD, 128>>>(memory, last_update, timestamps, edge_features,
                             time_w, time_b, sources, destinations, N, E);
    k_gemm2<<<dim3(5, MtRows), 256, SM_TOT>>>(pMh, KP_M, pWih, pWil, NP_G,
                                              gru_bi, pGI, N, G3, KP_M, 0, 0);
    k_memconv<<<(NPAD * KP_S + 255) / 256, 256>>>(memory, N);
    k_prep_wh<<<(KP_S * NP_G + 255) / 256, 256>>>(gru_Wh);
    k_gemm2<<<dim3(5, MtRows), 256, SM_TOT>>>(pMemh, KP_S, pWhh, pWhl, NP_G,
                                              gru_bh, pGH, N, G3, KP_S, 0, 0);
    k_gate<<<(NPAD * KP_S + 255) / 256, 256>>>(memory, node_features, N);

    // extended QKV = h @ [Wq1|Wk1|Wv1|Wc]
    k_prep_qkv<<<(KP_S * NP_Q + 255) / 256, 256>>>(Wq, Wk, Wv);
    k_gemm2<<<dim3(6, MtRows), 256, SM_TOT>>>(pHh, KP_S, pQh, pQl, NP_Q,
                                              nullptr, pQKV, N, NP_Q, KP_S, 0, 0);

    // attention: softmax + gathers; weight terms via GEMM
    k_prep_qconst<<<1, 256>>>(Wq, Wk, time_b);
    k_prep_bv<<<(WT_K * 256 + 255) / 256, 256>>>(Wv);
    k_attn<<<NPAD, 128>>>(neighbor_idx, neighbor_ts, time_w, time_b,
                          timestamps, N, E);
    // agg += wt @ Wv2blk  (accumulate onto neighbor part)
    k_gemm2<<<dim3(2, MtRows), 256, SM_TOT>>>(pWtb, WT_K, pBVh, pBVl, 256,
                                              nullptr, pAggF, NPAD, KP_S, WT_K, 1, 0);
    k_aggsplit<<<(NPAD * KP_S + 255) / 256, 256>>>(N);

    // MLP
    k_prep_w1<<<(KP_S * NP_S + 255) / 256, 256>>>(W1);
    k_prep_w2<<<(KP_S * NP_S + 255) / 256, 256>>>(W2);
    k_gemm2<<<dim3(2, MtRows), 256, SM_TOT>>>(pHh, KP_S, pW1ah, pW1al, NP_S,
                                              b1, pT1, N, MEMD, KP_S, 0, 0);
    k_gemm2<<<dim3(2, MtRows), 256, SM_TOT>>>(pAh, KP_S, pW1bh, pW1bl, NP_S,
                                              nullptr, pT1, N, MEMD, KP_S, 1, 1);
    k_t1split<<<(NPAD * KP_S + 255) / 256, 256>>>(N);
    k_gemm2<<<dim3(2, MtRows), 256, SM_TOT>>>(pT1h, KP_S, pW2h, pW2l, NP_S,
                                              b2, pEmb, N, MEMD, KP_S, 0, 0);

    // classifier head
    k_reduce1<<<RB, 192>>>(N);
    k_final<<<1, 192>>>(fc2_w, fc2_b, (float*)d_out, N);
}